// round 3
// baseline (speedup 1.0000x reference)
#include <cuda_runtime.h>
#include <cuda_bf16.h>

#define BB 64

// ---------- static device scratch (no allocations) ----------
__device__ float g_Mt[1024 * 1024];     // Mt[d*1024+k] = M[k][d]
__device__ float g_mpos[1024];
__device__ float g_meanS[BB * 588];
__device__ float g_meanO[BB * 588];
__device__ float g_npool[BB * 9408];
__device__ float g_part[3145728];
__device__ float g_feats[BB * 3 * 1024];
__device__ float g_dct[192 * 1024];
__device__ float g_t[192 * 1024];
__device__ float g_q[192 * 1024];
__device__ float g_k[192 * 1024];
__device__ float g_wofc[1024];
__device__ float g_wvofc[1024];
__device__ float g_vproj[192];
__device__ float g_tokfc[192];

// ---------- helpers ----------
__device__ __forceinline__ unsigned long long pk2(float lo, float hi) {
    unsigned long long r;
    asm("mov.b64 %0,{%1,%2};" : "=l"(r) : "r"(__float_as_uint(lo)), "r"(__float_as_uint(hi)));
    return r;
}
__device__ __forceinline__ void fma2(unsigned long long& acc, unsigned long long a, unsigned long long b) {
    asm("fma.rn.f32x2 %0, %1, %2, %0;" : "+l"(acc) : "l"(a), "l"(b));
}
__device__ __forceinline__ float blk_sum256(float v) {
    __shared__ float sb[8];
    int lane = threadIdx.x & 31, w = threadIdx.x >> 5;
    for (int o = 16; o; o >>= 1) v += __shfl_xor_sync(0xffffffffu, v, o);
    if (!lane) sb[w] = v;
    __syncthreads();
    float t = 0.f;
#pragma unroll
    for (int i = 0; i < 8; i++) t += sb[i];
    __syncthreads();
    return t;
}

// ---------- DCT matrix (matches JAX fp32 arg rounding; accurate cos) ----------
__global__ void k_build_M() {
    int idx = blockIdx.x * 256 + threadIdx.x;
    int d = idx >> 10, k = idx & 1023;
    float t1 = __fmul_rn(3.14159265358979323846f, (float)d + 0.5f);
    float t2 = __fmul_rn(t1, (float)k);
    float t3 = __fmul_rn(t2, 0.0009765625f);           // exact /1024
    float q = rintf(t3 * 0.6366197723675814f);          // 2/pi
    float r = __fmaf_rn(q, -1.57079637050628662109375f, t3);
    r = __fmaf_rn(q, 4.37113900018624283e-8f, r);
    int qi = ((int)q) & 3;
    float cr = cosf(r), sr = sinf(r);
    float c = (qi == 0) ? cr : (qi == 1) ? -sr : (qi == 2) ? -cr : sr;
    float s = (k == 0) ? 0.03125f : sqrtf(0.001953125f);
    g_Mt[idx] = c * s;
}

// ---------- mean pos_emb over 256 tokens ----------
__global__ void k_mpos(const float* __restrict__ pos) {
    int d = blockIdx.x * 256 + threadIdx.x;
    float s = 0.f;
    for (int t = 0; t < 256; t++) s += pos[t * 1024 + d];
    g_mpos[d] = s * (1.0f / 256.0f);
}

// ---------- mat-vec precomputes ----------
__global__ void k_wofc(const float* __restrict__ Wo, const float* __restrict__ Wfc) {
    int row = blockIdx.x * 8 + (threadIdx.x >> 5), lane = threadIdx.x & 31;
    const float* wr = Wo + (size_t)row * 1024;
    float s = 0.f;
    for (int j = lane; j < 1024; j += 32) s += wr[j] * Wfc[j];
    for (int o = 16; o; o >>= 1) s += __shfl_xor_sync(0xffffffffu, s, o);
    if (!lane) g_wofc[row] = s;
}
__global__ void k_wvofc(const float* __restrict__ Wv) {
    int row = blockIdx.x * 8 + (threadIdx.x >> 5), lane = threadIdx.x & 31;
    const float* wr = Wv + (size_t)row * 1024;
    float s = 0.f;
    for (int j = lane; j < 1024; j += 32) s += wr[j] * g_wofc[j];
    for (int o = 16; o; o >>= 1) s += __shfl_xor_sync(0xffffffffu, s, o);
    if (!lane) g_wvofc[row] = s;
}

// ---------- noise pooling: npool = pool4(x) - pool8(x) ----------
__global__ void k_pool(const float* __restrict__ x) {
    int bc = blockIdx.x;
    const float* plane = x + (size_t)bc * (224 * 224);
    __shared__ float p4[3136];
    for (int cell = threadIdx.x; cell < 3136; cell += 256) {
        int i = cell / 56, j = cell % 56;
        const float* p = plane + (i * 4) * 224 + j * 4;
        float s = 0.f;
#pragma unroll
        for (int r = 0; r < 4; r++)
            s += p[r * 224] + p[r * 224 + 1] + p[r * 224 + 2] + p[r * 224 + 3];
        p4[cell] = s;
    }
    __syncthreads();
    for (int cell = threadIdx.x; cell < 3136; cell += 256) {
        int i = cell / 56, j = cell % 56;
        int i0 = i & ~1, j0 = j & ~1;
        float s8 = p4[i0 * 56 + j0] + p4[i0 * 56 + j0 + 1] +
                   p4[(i0 + 1) * 56 + j0] + p4[(i0 + 1) * 56 + j0 + 1];
        g_npool[(size_t)bc * 3136 + cell] = p4[cell] * 0.0625f - s8 * 0.015625f;
    }
}

// ---------- per-(c, y%14, x%14) bin means: orig + shuffled ----------
__global__ void k_bins(const float* __restrict__ x, const int* __restrict__ sidx,
                       const int* __restrict__ rot, const int* __restrict__ fh,
                       const int* __restrict__ fw) {
    int bc = blockIdx.x, b = bc / 3, c = bc % 3;
    const float* plane = x + (size_t)bc * (224 * 224);
    __shared__ int sm_m[49], sm_k[49], sm_h[49], sm_w[49];
    if (threadIdx.x < 49) {
        int n = threadIdx.x;
        sm_m[n] = sidx[n];
        sm_k[n] = rot[b * 49 + n];
        sm_h[n] = fh[b * 49 + n];
        sm_w[n] = fw[b * 49 + n];
    }
    __syncthreads();
    int t = threadIdx.x;
    if (t < 196) {
        int dy = t / 14, dx = t % 14;
        float s = 0.f;
        for (int ii = 0; ii < 16; ii++) {
            const float* row = plane + (ii * 14 + dy) * 224;
#pragma unroll
            for (int jj = 0; jj < 16; jj++) s += row[jj * 14 + dx];
        }
        g_meanO[b * 588 + c * 196 + t] = s * (1.0f / 256.0f);
    } else if (t >= 256 && t < 452) {
        int bin = t - 256, dy = bin / 14, dx = bin % 14;
        float s = 0.f;
        for (int ii = 0; ii < 16; ii++) {
            int y = ii * 14 + dy;
            int pr = y >> 5, r = y & 31;
            for (int jj = 0; jj < 16; jj++) {
                int xx = jj * 14 + dx;
                int pc = xx >> 5, cc = xx & 31;
                int n = pr * 7 + pc;
                int m = sm_m[n];
                int c1 = sm_w[n] ? 31 - cc : cc;
                int r1 = sm_h[n] ? 31 - r : r;
                int k = sm_k[n], sr, sc;
                if (k == 0)      { sr = r1;      sc = c1;      }
                else if (k == 1) { sr = c1;      sc = 31 - r1; }
                else if (k == 2) { sr = 31 - r1; sc = 31 - c1; }
                else             { sr = 31 - c1; sc = r1;      }
                s += plane[((m / 7) * 32 + sr) * 224 + (m % 7) * 32 + sc];
            }
        }
        g_meanS[b * 588 + c * 196 + bin] = s * (1.0f / 256.0f);
    }
}

// ---------- split-K GEMM: 64-row tile x 128 cols per block ----------
// A selectors: 0=g_meanS 1=g_meanO 2=g_npool 3=g_feats 4=g_t
__device__ __forceinline__ const float* asrc(int s) {
    switch (s) {
        case 0: return g_meanS;
        case 1: return g_meanO;
        case 2: return g_npool;
        case 3: return g_feats;
        default: return g_t;
    }
}
__global__ void __launch_bounds__(256) k_gemm(
    int asel0, int asel1, const float* __restrict__ W0, const float* __restrict__ W1,
    int use_Mt, long long part_off, int K, int S, int nrt)
{
    int z = blockIdx.z;
    int mat = z / nrt, rt = z - mat * nrt;
    const float* A = asrc(mat ? asel1 : asel0) + (size_t)(rt * 64) * K;
    const float* W = use_Mt ? g_Mt : (mat ? W1 : W0);
    int tid = threadIdx.x;
    int c0 = blockIdx.x * 128 + (tid & 63);
    int row0 = (tid >> 6) * 16;
    int kslice = K / S;
    int kbeg = blockIdx.y * kslice, kend = kbeg + kslice;

    __shared__ __align__(16) float a_sm[16 * 68];
    unsigned long long acc[16];
#pragma unroll
    for (int i = 0; i < 16; i++) acc[i] = 0ULL;

    for (int k0 = kbeg; k0 < kend; k0 += 16) {
        int cb = min(16, kend - k0);
        __syncthreads();
        for (int idx = tid; idx < 1024; idx += 256) {
            int m = idx >> 4, kk = idx & 15;
            a_sm[kk * 68 + m] = (kk < cb) ? A[(size_t)m * K + k0 + kk] : 0.f;
        }
        __syncthreads();
        const float* wp = W + (size_t)k0 * 1024 + c0;
#pragma unroll 4
        for (int kk = 0; kk < cb; kk++) {
            float w0 = wp[(size_t)kk * 1024];
            float w1 = wp[(size_t)kk * 1024 + 64];
            unsigned long long w0x = pk2(w0, w0), w1x = pk2(w1, w1);
            const float4* ap = reinterpret_cast<const float4*>(a_sm + kk * 68 + row0);
            float4 a0 = ap[0], a1 = ap[1], a2 = ap[2], a3 = ap[3];
            unsigned long long p0 = pk2(a0.x, a0.y), p1 = pk2(a0.z, a0.w);
            unsigned long long p2 = pk2(a1.x, a1.y), p3 = pk2(a1.z, a1.w);
            unsigned long long p4 = pk2(a2.x, a2.y), p5 = pk2(a2.z, a2.w);
            unsigned long long p6 = pk2(a3.x, a3.y), p7 = pk2(a3.z, a3.w);
            fma2(acc[0], p0, w0x); fma2(acc[1], p1, w0x);
            fma2(acc[2], p2, w0x); fma2(acc[3], p3, w0x);
            fma2(acc[4], p4, w0x); fma2(acc[5], p5, w0x);
            fma2(acc[6], p6, w0x); fma2(acc[7], p7, w0x);
            fma2(acc[8], p0, w1x); fma2(acc[9], p1, w1x);
            fma2(acc[10], p2, w1x); fma2(acc[11], p3, w1x);
            fma2(acc[12], p4, w1x); fma2(acc[13], p5, w1x);
            fma2(acc[14], p6, w1x); fma2(acc[15], p7, w1x);
        }
    }
    float* po = g_part + part_off + ((size_t)(mat * S + blockIdx.y) * nrt + rt) * 65536;
#pragma unroll
    for (int j = 0; j < 8; j++) {
        unsigned lo, hi;
        asm("mov.b64 {%0,%1}, %2;" : "=r"(lo), "=r"(hi) : "l"(acc[j]));
        po[(size_t)(row0 + 2 * j) * 1024 + c0] = __uint_as_float(lo);
        po[(size_t)(row0 + 2 * j + 1) * 1024 + c0] = __uint_as_float(hi);
        asm("mov.b64 {%0,%1}, %2;" : "=r"(lo), "=r"(hi) : "l"(acc[8 + j]));
        po[(size_t)(row0 + 2 * j) * 1024 + c0 + 64] = __uint_as_float(lo);
        po[(size_t)(row0 + 2 * j + 1) * 1024 + c0 + 64] = __uint_as_float(hi);
    }
}

// ---------- deterministic reductions ----------
// which: 0 -> g_dct, 1 -> g_q, 2 -> g_k
__global__ void k_reduce(long long part_off, int which, int S) {
    int i = blockIdx.x * 256 + threadIdx.x;           // n = 196608
    float s = 0.f;
    for (int y = 0; y < S; y++) s += g_part[part_off + (size_t)y * 196608 + i];
    float* out = (which == 0) ? g_dct : (which == 1) ? g_q : g_k;
    out[i] = s;
}
__global__ void k_reduce_noise() {
    int i = blockIdx.x * 256 + threadIdx.x;           // 65536
    float s = 0.f;
#pragma unroll
    for (int y = 0; y < 24; y++) s += g_part[1572864 + (size_t)y * 65536 + i];
    int b = i >> 10, d = i & 1023;
    g_feats[((size_t)b * 3 + 2) * 1024 + d] = s;
}
__global__ void k_reduce_ln_branch(const float* __restrict__ gg, const float* __restrict__ bb) {
    int z = blockIdx.x >> 6, b = blockIdx.x & 63;
    const float* base = g_part + (size_t)z * 12 * 65536 + (size_t)b * 1024;
    float v[4], s = 0.f, q = 0.f;
#pragma unroll
    for (int i = 0; i < 4; i++) {
        int d = threadIdx.x + i * 256;
        float xv = g_mpos[d];
#pragma unroll
        for (int y = 0; y < 12; y++) xv += base[(size_t)y * 65536 + d];
        v[i] = xv; s += xv; q += xv * xv;
    }
    s = blk_sum256(s); q = blk_sum256(q);
    float mean = s * (1.0f / 1024.0f);
    float inv = rsqrtf(q * (1.0f / 1024.0f) - mean * mean + 1e-5f);
#pragma unroll
    for (int i = 0; i < 4; i++) {
        int d = threadIdx.x + i * 256;
        g_feats[((size_t)b * 3 + z) * 1024 + d] = (v[i] - mean) * inv * gg[d] + bb[d];
    }
}

// ---------- token layernorm + fc/vproj dots ----------
__global__ void k_ln_tokens(const float* __restrict__ gg, const float* __restrict__ bb,
                            const float* __restrict__ wfc) {
    int r = blockIdx.x;
    float x[4], s = 0.f, q = 0.f;
#pragma unroll
    for (int i = 0; i < 4; i++) {
        int d = threadIdx.x + i * 256;
        x[i] = g_dct[(size_t)r * 1024 + d];
        s += x[i]; q += x[i] * x[i];
    }
    s = blk_sum256(s); q = blk_sum256(q);
    float mean = s * (1.0f / 1024.0f);
    float inv = rsqrtf(q * (1.0f / 1024.0f) - mean * mean + 1e-5f);
    float dt = 0.f, dv = 0.f;
#pragma unroll
    for (int i = 0; i < 4; i++) {
        int d = threadIdx.x + i * 256;
        float tv = (x[i] - mean) * inv * gg[d] + bb[d];
        g_t[(size_t)r * 1024 + d] = tv;
        dt += x[i] * wfc[d];
        dv += tv * g_wvofc[d];
    }
    dt = blk_sum256(dt); dv = blk_sum256(dv);
    if (threadIdx.x == 0) { g_tokfc[r] = dt; g_vproj[r] = dv; }
}

// ---------- final: 3x3 attention + epilogue ----------
__global__ void k_final(const float* __restrict__ bfc, float* __restrict__ out) {
    int b = blockIdx.x, lane = threadIdx.x;
    const float* qb = g_q + (size_t)b * 3 * 1024;
    const float* kb = g_k + (size_t)b * 3 * 1024;
    float s[9];
#pragma unroll
    for (int p = 0; p < 9; p++) s[p] = 0.f;
    for (int d = lane; d < 1024; d += 32) {
        float q0 = qb[d], q1 = qb[1024 + d], q2 = qb[2048 + d];
        float k0 = kb[d], k1 = kb[1024 + d], k2 = kb[2048 + d];
        s[0] += q0 * k0; s[1] += q0 * k1; s[2] += q0 * k2;
        s[3] += q1 * k0; s[4] += q1 * k1; s[5] += q1 * k2;
        s[6] += q2 * k0; s[7] += q2 * k1; s[8] += q2 * k2;
    }
#pragma unroll
    for (int p = 0; p < 9; p++)
        for (int o = 16; o; o >>= 1) s[p] += __shfl_xor_sync(0xffffffffu, s[p], o);
    if (lane == 0) {
        float w0 = 0.f, w1 = 0.f, w2 = 0.f;
#pragma unroll
        for (int n = 0; n < 3; n++) {
            float a = s[n * 3] * 0.03125f, c = s[n * 3 + 1] * 0.03125f, e = s[n * 3 + 2] * 0.03125f;
            float mx = fmaxf(a, fmaxf(c, e));
            float e0 = expf(a - mx), e1 = expf(c - mx), e2 = expf(e - mx);
            float is = 1.0f / (e0 + e1 + e2);
            w0 += e0 * is; w1 += e1 * is; w2 += e2 * is;
        }
        float r = (w0 * g_vproj[b * 3] + w1 * g_vproj[b * 3 + 1] + w2 * g_vproj[b * 3 + 2]) * (1.0f / 3.0f);
        r += (g_tokfc[b * 3] + g_tokfc[b * 3 + 1] + g_tokfc[b * 3 + 2]) * (1.0f / 3.0f);
        out[b] = r + bfc[0];
    }
}

// ---------- launch ----------
extern "C" void kernel_launch(void* const* d_in, const int* in_sizes, int n_in,
                              void* d_out, int out_size) {
    (void)in_sizes; (void)n_in; (void)out_size;
    const float* x      = (const float*)d_in[0];
    const int*   sidx   = (const int*)d_in[1];
    const int*   rot    = (const int*)d_in[2];
    const int*   fh     = (const int*)d_in[3];
    const int*   fw     = (const int*)d_in[4];
    const float* W_pe   = (const float*)d_in[5];
    const float* pos    = (const float*)d_in[6];
    const float* ln_g   = (const float*)d_in[7];
    const float* ln_b   = (const float*)d_in[8];
    const float* W_no   = (const float*)d_in[9];
    const float* Wq     = (const float*)d_in[10];
    const float* Wk     = (const float*)d_in[11];
    const float* Wv     = (const float*)d_in[12];
    const float* Wo     = (const float*)d_in[13];
    const float* ah_g   = (const float*)d_in[14];
    const float* ah_b   = (const float*)d_in[15];
    const float* W_fc   = (const float*)d_in[16];
    const float* b_fc   = (const float*)d_in[17];
    float* out = (float*)d_out;

    k_build_M<<<4096, 256>>>();
    k_mpos<<<4, 256>>>(pos);
    k_wofc<<<128, 256>>>(Wo, W_fc);
    k_wvofc<<<128, 256>>>(Wv);
    k_pool<<<192, 256>>>(x);
    k_bins<<<192, 512>>>(x, sidx, rot, fh, fw);

    // branches: meanS/meanO (64x588) @ W_pe, split-K 12, mats=2 -> part[0 .. 24*65536)
    k_gemm<<<dim3(8, 12, 2), 256>>>(0, 1, W_pe, W_pe, 0, 0, 588, 12, 1);
    // noise: npool (64x9408) @ W_noise, split-K 24 -> part[1572864 ..)
    k_gemm<<<dim3(8, 24, 1), 256>>>(2, 2, W_no, W_no, 0, 1572864, 9408, 24, 1);
    k_reduce_ln_branch<<<128, 256>>>(ln_g, ln_b);
    k_reduce_noise<<<256, 256>>>();

    // DCT: feats (192x1024) @ Mt, split-K 8, 3 row tiles
    k_gemm<<<dim3(8, 8, 3), 256>>>(3, 3, W_pe, W_pe, 1, 0, 1024, 8, 3);
    k_reduce<<<768, 256>>>(0, 0, 8);

    k_ln_tokens<<<192, 256>>>(ah_g, ah_b, W_fc);

    // q,k: t (192x1024) @ Wq / Wk, split-K 4, 3 row tiles, 2 mats
    k_gemm<<<dim3(8, 4, 6), 256>>>(4, 4, Wq, Wk, 0, 0, 1024, 4, 3);
    k_reduce<<<768, 256>>>(0, 1, 4);
    k_reduce<<<768, 256>>>(4LL * 196608, 2, 4);

    k_final<<<64, 32>>>(b_fc, out);
}

// round 4
// speedup vs baseline: 1.0281x; 1.0281x over previous
#include <cuda_runtime.h>
#include <cuda_bf16.h>

// ---------- static device scratch ----------
__device__ float g_Mt[1024 * 1024];
__device__ float g_mpart[8 * 1024];
__device__ float g_meanS[64 * 588];
__device__ float g_meanO[64 * 588];
__device__ float g_npool[64 * 9408];
__device__ float g_part[3145728];
__device__ float g_feats[64 * 3 * 1024];
__device__ float g_t[192 * 1024];
__device__ float g_wofc[1024];
__device__ float g_wvofc[1024];
__device__ float g_vproj[192];
__device__ float g_tokfc[192];

// ---------- helpers ----------
__device__ __forceinline__ unsigned long long pk2(float lo, float hi) {
    unsigned long long r;
    asm("mov.b64 %0,{%1,%2};" : "=l"(r) : "r"(__float_as_uint(lo)), "r"(__float_as_uint(hi)));
    return r;
}
__device__ __forceinline__ void fma2(unsigned long long& acc, unsigned long long a, unsigned long long b) {
    asm("fma.rn.f32x2 %0, %1, %2, %0;" : "+l"(acc) : "l"(a), "l"(b));
}
__device__ __forceinline__ float blk_sum256(float v) {
    __shared__ float sb[8];
    int lane = threadIdx.x & 31, w = threadIdx.x >> 5;
    for (int o = 16; o; o >>= 1) v += __shfl_xor_sync(0xffffffffu, v, o);
    if (!lane) sb[w] = v;
    __syncthreads();
    float t = 0.f;
#pragma unroll
    for (int i = 0; i < 8; i++) t += sb[i];
    __syncthreads();
    return t;
}

// ---------- fused setup: DCT matrix + pos-emb partials + Wo@Wfc ----------
__global__ void __launch_bounds__(256) k_setup(const float* __restrict__ pos,
                                               const float* __restrict__ Wo,
                                               const float* __restrict__ Wfc) {
    int bx = blockIdx.x, tid = threadIdx.x;
    if (bx < 4096) {                               // DCT matrix, JAX fp32 arg rounding
        int idx = bx * 256 + tid;
        int d = idx >> 10, k = idx & 1023;
        float t1 = __fmul_rn(3.14159265358979323846f, (float)d + 0.5f);
        float t2 = __fmul_rn(t1, (float)k);
        float t3 = __fmul_rn(t2, 0.0009765625f);
        float q = rintf(t3 * 0.6366197723675814f);
        float r = __fmaf_rn(q, -1.57079637050628662109375f, t3);
        r = __fmaf_rn(q, 4.37113900018624283e-8f, r);
        int qi = ((int)q) & 3;
        float cr = cosf(r), sr = sinf(r);
        float c = (qi == 0) ? cr : (qi == 1) ? -sr : (qi == 2) ? -cr : sr;
        float s = (k == 0) ? 0.03125f : sqrtf(0.001953125f);
        g_Mt[idx] = c * s;
    } else if (bx < 4104) {                        // pos-emb partial sums (32 tokens each)
        int p = bx - 4096;
#pragma unroll
        for (int qq = 0; qq < 4; qq++) {
            int d = tid + qq * 256;
            float s = 0.f;
#pragma unroll 4
            for (int t = 0; t < 32; t++) s += pos[(p * 32 + t) * 1024 + d];
            g_mpart[p * 1024 + d] = s;
        }
    } else {                                       // wofc = Wo @ Wfc (2 warps per row)
        int bl = bx - 4104;
        int row = bl * 4 + (tid >> 6);
        int l64 = tid & 63;
        const float* wr = Wo + (size_t)row * 1024;
        float s = 0.f;
#pragma unroll 16
        for (int it = 0; it < 16; it++) s += wr[it * 64 + l64] * Wfc[it * 64 + l64];
        for (int o = 16; o; o >>= 1) s += __shfl_xor_sync(0xffffffffu, s, o);
        __shared__ float ss[8];
        if (!(tid & 31)) ss[tid >> 5] = s;
        __syncthreads();
        if (tid < 4) g_wofc[bl * 4 + tid] = ss[2 * tid] + ss[2 * tid + 1];
    }
}
__global__ void __launch_bounds__(256) k_wvofc(const float* __restrict__ Wv) {
    int row = blockIdx.x * 4 + (threadIdx.x >> 6), l64 = threadIdx.x & 63;
    const float* wr = Wv + (size_t)row * 1024;
    float s = 0.f;
#pragma unroll 16
    for (int it = 0; it < 16; it++) s += wr[it * 64 + l64] * g_wofc[it * 64 + l64];
    for (int o = 16; o; o >>= 1) s += __shfl_xor_sync(0xffffffffu, s, o);
    __shared__ float ss[8];
    if (!(threadIdx.x & 31)) ss[threadIdx.x >> 5] = s;
    __syncthreads();
    if (threadIdx.x < 4) g_wvofc[blockIdx.x * 4 + threadIdx.x] = ss[2 * threadIdx.x] + ss[2 * threadIdx.x + 1];
}

// ---------- fused per-plane: load to smem, pools + orig bins + shuffled bins ----------
__global__ void __launch_bounds__(512) k_planes(const float* __restrict__ x,
                                                const int* __restrict__ sidx,
                                                const int* __restrict__ rot,
                                                const int* __restrict__ fh,
                                                const int* __restrict__ fw) {
    extern __shared__ float sm[];
    float* pl = sm;                 // 224 rows x 225 stride
    float* p4 = sm + 225 * 224;     // 56x56
    int bc = blockIdx.x, b = bc / 3, c = bc % 3, tid = threadIdx.x;
    const float* plane = x + (size_t)bc * 50176;

    __shared__ int sm_m[49], sm_k[49], sm_h[49], sm_w[49];
    if (tid < 49) {
        sm_m[tid] = sidx[tid];
        sm_k[tid] = rot[b * 49 + tid];
        sm_h[tid] = fh[b * 49 + tid];
        sm_w[tid] = fw[b * 49 + tid];
    }
    for (int idx = tid; idx < 50176; idx += 512) {
        int i = idx / 224, j = idx - i * 224;
        pl[i * 225 + j] = plane[idx];
    }
    __syncthreads();
    for (int cell = tid; cell < 3136; cell += 512) {
        int i = cell / 56, j = cell - (cell / 56) * 56;
        const float* p = pl + (i * 4) * 225 + j * 4;
        float s = 0.f;
#pragma unroll
        for (int r = 0; r < 4; r++)
            s += p[r * 225] + p[r * 225 + 1] + p[r * 225 + 2] + p[r * 225 + 3];
        p4[cell] = s;
    }
    __syncthreads();
    for (int cell = tid; cell < 3136; cell += 512) {
        int i = cell / 56, j = cell - (cell / 56) * 56;
        int i0 = i & ~1, j0 = j & ~1;
        float s8 = p4[i0 * 56 + j0] + p4[i0 * 56 + j0 + 1] +
                   p4[(i0 + 1) * 56 + j0] + p4[(i0 + 1) * 56 + j0 + 1];
        g_npool[(size_t)bc * 3136 + cell] = p4[cell] * 0.0625f - s8 * 0.015625f;
    }
    if (tid < 196) {                               // original-branch bins
        int dy = tid / 14, dx = tid - (tid / 14) * 14;
        float s = 0.f;
        for (int ii = 0; ii < 16; ii++) {
            const float* row = pl + (ii * 14 + dy) * 225;
#pragma unroll
            for (int jj = 0; jj < 16; jj++) s += row[jj * 14 + dx];
        }
        g_meanO[b * 588 + c * 196 + tid] = s * (1.0f / 256.0f);
    } else if (tid >= 256 && tid < 452) {          // shuffled-branch bins (inverse map)
        int bin = tid - 256, dy = bin / 14, dx = bin - (bin / 14) * 14;
        float s = 0.f;
        for (int ii = 0; ii < 16; ii++) {
            int y = ii * 14 + dy;
            int pr = y >> 5, r = y & 31;
#pragma unroll 4
            for (int jj = 0; jj < 16; jj++) {
                int xx = jj * 14 + dx;
                int pc = xx >> 5, cc = xx & 31;
                int n = pr * 7 + pc;
                int m = sm_m[n];
                int c1 = sm_w[n] ? 31 - cc : cc;
                int r1 = sm_h[n] ? 31 - r : r;
                int k = sm_k[n], sr, sc;
                if (k == 0)      { sr = r1;      sc = c1;      }
                else if (k == 1) { sr = c1;      sc = 31 - r1; }
                else if (k == 2) { sr = 31 - r1; sc = 31 - c1; }
                else             { sr = 31 - c1; sc = r1;      }
                s += pl[((m / 7) * 32 + sr) * 225 + (m % 7) * 32 + sc];
            }
        }
        g_meanS[b * 588 + c * 196 + bin] = s * (1.0f / 256.0f);
    }
}

// ---------- GEMM body: 64 rows x 128 cols per block, packed f32x2 ----------
__device__ __forceinline__ void gemm_body(const float* __restrict__ A, const float* __restrict__ W,
                                          float* __restrict__ po, int K, int kbeg, int kend,
                                          float* a_sm) {
    int tid = threadIdx.x;
    int c0 = blockIdx.x * 128 + (tid & 63);
    int row0 = (tid >> 6) * 16;
    unsigned long long acc[16];
#pragma unroll
    for (int i = 0; i < 16; i++) acc[i] = 0ULL;
    for (int k0 = kbeg; k0 < kend; k0 += 16) {
        int cb = min(16, kend - k0);
        __syncthreads();
        for (int idx = tid; idx < 1024; idx += 256) {
            int m = idx >> 4, kk = idx & 15;
            a_sm[kk * 68 + m] = (kk < cb) ? A[(size_t)m * K + k0 + kk] : 0.f;
        }
        __syncthreads();
        const float* wp = W + (size_t)k0 * 1024 + c0;
#pragma unroll 4
        for (int kk = 0; kk < cb; kk++) {
            float w0 = wp[(size_t)kk * 1024];
            float w1 = wp[(size_t)kk * 1024 + 64];
            unsigned long long w0x = pk2(w0, w0), w1x = pk2(w1, w1);
            const float4* ap = reinterpret_cast<const float4*>(a_sm + kk * 68 + row0);
            float4 a0 = ap[0], a1 = ap[1], a2 = ap[2], a3 = ap[3];
            unsigned long long p0 = pk2(a0.x, a0.y), p1 = pk2(a0.z, a0.w);
            unsigned long long p2 = pk2(a1.x, a1.y), p3 = pk2(a1.z, a1.w);
            unsigned long long p4 = pk2(a2.x, a2.y), p5 = pk2(a2.z, a2.w);
            unsigned long long p6 = pk2(a3.x, a3.y), p7 = pk2(a3.z, a3.w);
            fma2(acc[0], p0, w0x); fma2(acc[1], p1, w0x);
            fma2(acc[2], p2, w0x); fma2(acc[3], p3, w0x);
            fma2(acc[4], p4, w0x); fma2(acc[5], p5, w0x);
            fma2(acc[6], p6, w0x); fma2(acc[7], p7, w0x);
            fma2(acc[8], p0, w1x); fma2(acc[9], p1, w1x);
            fma2(acc[10], p2, w1x); fma2(acc[11], p3, w1x);
            fma2(acc[12], p4, w1x); fma2(acc[13], p5, w1x);
            fma2(acc[14], p6, w1x); fma2(acc[15], p7, w1x);
        }
    }
#pragma unroll
    for (int j = 0; j < 8; j++) {
        unsigned lo, hi;
        asm("mov.b64 {%0,%1}, %2;" : "=r"(lo), "=r"(hi) : "l"(acc[j]));
        po[(size_t)(row0 + 2 * j) * 1024 + c0] = __uint_as_float(lo);
        po[(size_t)(row0 + 2 * j + 1) * 1024 + c0] = __uint_as_float(hi);
        asm("mov.b64 {%0,%1}, %2;" : "=r"(lo), "=r"(hi) : "l"(acc[8 + j]));
        po[(size_t)(row0 + 2 * j) * 1024 + c0 + 64] = __uint_as_float(lo);
        po[(size_t)(row0 + 2 * j + 1) * 1024 + c0 + 64] = __uint_as_float(hi);
    }
}

// merged branch(2 mats, K=588, S=12) + noise(K=9408, S=24)
__global__ void __launch_bounds__(256) k_gemm_bn(const float* __restrict__ W_pe,
                                                 const float* __restrict__ W_no) {
    __shared__ __align__(16) float a_sm[16 * 68];
    int z = blockIdx.z;
    if (z < 24) {
        int mat = z / 12, y = z - mat * 12;
        const float* A = mat ? g_meanO : g_meanS;
        gemm_body(A, W_pe, g_part + (size_t)z * 65536, 588, y * 49, y * 49 + 49, a_sm);
    } else {
        int y = z - 24;
        gemm_body(g_npool, W_no, g_part + 1572864 + (size_t)y * 65536, 9408, y * 392, y * 392 + 392, a_sm);
    }
}
// generic: asel 3=g_feats 4=g_t
__global__ void __launch_bounds__(256) k_gemm(int asel, const float* __restrict__ W0,
                                              const float* __restrict__ W1, int use_Mt,
                                              int K, int S, int nrt) {
    __shared__ __align__(16) float a_sm[16 * 68];
    int z = blockIdx.z;
    int mat = z / nrt, rt = z - mat * nrt;
    const float* A = ((asel == 3) ? g_feats : g_t) + (size_t)(rt * 64) * K;
    const float* W = use_Mt ? g_Mt : (mat ? W1 : W0);
    int kslice = K / S, kbeg = blockIdx.y * kslice;
    float* po = g_part + ((size_t)(mat * S + blockIdx.y) * nrt + rt) * 65536;
    gemm_body(A, W, po, K, kbeg, kbeg + kslice, a_sm);
}

// ---------- merged reduce: branch LN (+pos-emb) and noise ----------
__global__ void __launch_bounds__(256) k_reduce_bn(const float* __restrict__ gg,
                                                   const float* __restrict__ bb) {
    int bx = blockIdx.x;
    if (bx < 128) {
        int z = bx >> 6, b = bx & 63;
        const float* base = g_part + (size_t)z * 12 * 65536 + (size_t)b * 1024;
        float v[4], s = 0.f, q = 0.f;
#pragma unroll
        for (int i = 0; i < 4; i++) {
            int d = threadIdx.x + i * 256;
            float mp = 0.f;
#pragma unroll
            for (int p = 0; p < 8; p++) mp += g_mpart[p * 1024 + d];
            float xv = mp * (1.0f / 256.0f);
#pragma unroll
            for (int y = 0; y < 12; y++) xv += base[(size_t)y * 65536 + d];
            v[i] = xv; s += xv; q += xv * xv;
        }
        s = blk_sum256(s); q = blk_sum256(q);
        float mean = s * (1.0f / 1024.0f);
        float inv = rsqrtf(q * (1.0f / 1024.0f) - mean * mean + 1e-5f);
#pragma unroll
        for (int i = 0; i < 4; i++) {
            int d = threadIdx.x + i * 256;
            g_feats[((size_t)b * 3 + z) * 1024 + d] = (v[i] - mean) * inv * gg[d] + bb[d];
        }
    } else {
        int i = (bx - 128) * 256 + threadIdx.x;    // 65536 noise elements
        float s = 0.f;
#pragma unroll
        for (int y = 0; y < 24; y++) s += g_part[1572864 + (size_t)y * 65536 + i];
        int b = i >> 10, d = i & 1023;
        g_feats[((size_t)b * 3 + 2) * 1024 + d] = s;
    }
}

// ---------- token LN + inline 8-way DCT partial reduce + fc/vproj dots ----------
__global__ void __launch_bounds__(256) k_ln_tokens(const float* __restrict__ gg,
                                                   const float* __restrict__ bb,
                                                   const float* __restrict__ wfc) {
    int r = blockIdx.x;
    float x[4], s = 0.f, q = 0.f;
#pragma unroll
    for (int i = 0; i < 4; i++) {
        int d = threadIdx.x + i * 256;
        float xv = 0.f;
#pragma unroll
        for (int y = 0; y < 8; y++) xv += g_part[(size_t)y * 196608 + (size_t)r * 1024 + d];
        x[i] = xv; s += xv; q += xv * xv;
    }
    s = blk_sum256(s); q = blk_sum256(q);
    float mean = s * (1.0f / 1024.0f);
    float inv = rsqrtf(q * (1.0f / 1024.0f) - mean * mean + 1e-5f);
    float dt = 0.f, dv = 0.f;
#pragma unroll
    for (int i = 0; i < 4; i++) {
        int d = threadIdx.x + i * 256;
        float tv = (x[i] - mean) * inv * gg[d] + bb[d];
        g_t[(size_t)r * 1024 + d] = tv;
        dt += x[i] * wfc[d];
        dv += tv * g_wvofc[d];
    }
    dt = blk_sum256(dt); dv = blk_sum256(dv);
    if (threadIdx.x == 0) { g_tokfc[r] = dt; g_vproj[r] = dv; }
}

// ---------- final: inline 4-way q/k partial reduce + 3x3 attention ----------
__global__ void __launch_bounds__(256) k_final(const float* __restrict__ bfc,
                                               float* __restrict__ out) {
    int b = blockIdx.x, tid = threadIdx.x;
    size_t bq[3], bk[3];
#pragma unroll
    for (int n = 0; n < 3; n++) {
        int r = b * 3 + n;
        bq[n] = (size_t)(r >> 6) * 65536 + (size_t)(r & 63) * 1024;
        bk[n] = 786432 + bq[n];
    }
    float a9[9];
#pragma unroll
    for (int p = 0; p < 9; p++) a9[p] = 0.f;
#pragma unroll
    for (int i = 0; i < 4; i++) {
        int d = tid + i * 256;
        float qv[3], kv[3];
#pragma unroll
        for (int n = 0; n < 3; n++) {
            float sq = 0.f, sk = 0.f;
#pragma unroll
            for (int y = 0; y < 4; y++) {
                sq += g_part[(size_t)y * 196608 + bq[n] + d];
                sk += g_part[(size_t)y * 196608 + bk[n] + d];
            }
            qv[n] = sq; kv[n] = sk;
        }
#pragma unroll
        for (int n = 0; n < 3; n++)
#pragma unroll
            for (int m = 0; m < 3; m++) a9[n * 3 + m] += qv[n] * kv[m];
    }
    __shared__ float red[8 * 9];
    int lane = tid & 31, w = tid >> 5;
#pragma unroll
    for (int p = 0; p < 9; p++) {
        float v = a9[p];
        for (int o = 16; o; o >>= 1) v += __shfl_xor_sync(0xffffffffu, v, o);
        if (!lane) red[w * 9 + p] = v;
    }
    __syncthreads();
    if (tid == 0) {
        float s[9];
#pragma unroll
        for (int p = 0; p < 9; p++) {
            float v = 0.f;
#pragma unroll
            for (int ww = 0; ww < 8; ww++) v += red[ww * 9 + p];
            s[p] = v;
        }
        float w0 = 0.f, w1 = 0.f, w2 = 0.f;
#pragma unroll
        for (int n = 0; n < 3; n++) {
            float a = s[n * 3] * 0.03125f, c = s[n * 3 + 1] * 0.03125f, e = s[n * 3 + 2] * 0.03125f;
            float mx = fmaxf(a, fmaxf(c, e));
            float e0 = expf(a - mx), e1 = expf(c - mx), e2 = expf(e - mx);
            float is = 1.0f / (e0 + e1 + e2);
            w0 += e0 * is; w1 += e1 * is; w2 += e2 * is;
        }
        float r = (w0 * g_vproj[b * 3] + w1 * g_vproj[b * 3 + 1] + w2 * g_vproj[b * 3 + 2]) * (1.0f / 3.0f);
        r += (g_tokfc[b * 3] + g_tokfc[b * 3 + 1] + g_tokfc[b * 3 + 2]) * (1.0f / 3.0f);
        out[b] = r + bfc[0];
    }
}

// ---------- launch ----------
extern "C" void kernel_launch(void* const* d_in, const int* in_sizes, int n_in,
                              void* d_out, int out_size) {
    (void)in_sizes; (void)n_in; (void)out_size;
    const float* x    = (const float*)d_in[0];
    const int*   sidx = (const int*)d_in[1];
    const int*   rot  = (const int*)d_in[2];
    const int*   fh   = (const int*)d_in[3];
    const int*   fw   = (const int*)d_in[4];
    const float* W_pe = (const float*)d_in[5];
    const float* pos  = (const float*)d_in[6];
    const float* ln_g = (const float*)d_in[7];
    const float* ln_b = (const float*)d_in[8];
    const float* W_no = (const float*)d_in[9];
    const float* Wq   = (const float*)d_in[10];
    const float* Wk   = (const float*)d_in[11];
    const float* Wv   = (const float*)d_in[12];
    const float* Wo   = (const float*)d_in[13];
    const float* ah_g = (const float*)d_in[14];
    const float* ah_b = (const float*)d_in[15];
    const float* W_fc = (const float*)d_in[16];
    const float* b_fc = (const float*)d_in[17];
    float* out = (float*)d_out;

    cudaFuncSetAttribute(k_planes, cudaFuncAttributeMaxDynamicSharedMemorySize, 215040);

    k_setup<<<4360, 256>>>(pos, Wo, W_fc);
    k_wvofc<<<256, 256>>>(Wv);
    k_planes<<<192, 512, 214144>>>(x, sidx, rot, fh, fw);
    k_gemm_bn<<<dim3(8, 1, 48), 256>>>(W_pe, W_no);
    k_reduce_bn<<<384, 256>>>(ln_g, ln_b);
    k_gemm<<<dim3(8, 8, 3), 256>>>(3, W_pe, W_pe, 1, 1024, 8, 3);   // DCT
    k_ln_tokens<<<192, 256>>>(ah_g, ah_b, W_fc);
    k_gemm<<<dim3(8, 4, 6), 256>>>(4, Wq, Wk, 0, 1024, 4, 3);       // q,k
    k_final<<<64, 256>>>(b_fc, out);
}

// round 7
// speedup vs baseline: 1.3684x; 1.3311x over previous
#include <cuda_runtime.h>
#include <cuda_bf16.h>

// ---------- static device scratch ----------
__device__ float g_Mt[1024 * 1024];
__device__ float g_mpart[8 * 1024];
__device__ float g_meanS[64 * 588];
__device__ float g_meanO[64 * 588];
__device__ float g_npool[64 * 9408];
__device__ float g_part[4718592];
__device__ float g_feats[64 * 3 * 1024];
__device__ float g_t[192 * 1024];
__device__ float g_wofc[1024];
__device__ float g_wvofc[1024];
__device__ float g_vproj[192];
__device__ float g_tokfc[192];

// ---------- helpers ----------
__device__ __forceinline__ unsigned long long pk2(float lo, float hi) {
    unsigned long long r;
    asm("mov.b64 %0,{%1,%2};" : "=l"(r) : "r"(__float_as_uint(lo)), "r"(__float_as_uint(hi)));
    return r;
}
__device__ __forceinline__ void fma2(unsigned long long& acc, unsigned long long a, unsigned long long b) {
    asm("fma.rn.f32x2 %0, %1, %2, %0;" : "+l"(acc) : "l"(a), "l"(b));
}
__device__ __forceinline__ float blk_sum256(float v) {
    __shared__ float sb[8];
    int lane = threadIdx.x & 31, w = threadIdx.x >> 5;
    for (int o = 16; o; o >>= 1) v += __shfl_xor_sync(0xffffffffu, v, o);
    if (!lane) sb[w] = v;
    __syncthreads();
    float t = 0.f;
#pragma unroll
    for (int i = 0; i < 8; i++) t += sb[i];
    __syncthreads();
    return t;
}

// ---------- fused setup: DCT matrix + pos-emb partials + Wo@Wfc ----------
__global__ void __launch_bounds__(256) k_setup(const float* __restrict__ pos,
                                               const float* __restrict__ Wo,
                                               const float* __restrict__ Wfc) {
    int bx = blockIdx.x, tid = threadIdx.x;
    if (bx < 4096) {                               // DCT matrix, JAX fp32 arg rounding
        int idx = bx * 256 + tid;
        int d = idx >> 10, k = idx & 1023;
        float t1 = __fmul_rn(3.14159265358979323846f, (float)d + 0.5f);
        float t2 = __fmul_rn(t1, (float)k);
        float t3 = __fmul_rn(t2, 0.0009765625f);
        float q = rintf(t3 * 0.6366197723675814f);
        float r = __fmaf_rn(q, -1.57079637050628662109375f, t3);
        r = __fmaf_rn(q, 4.37113900018624283e-8f, r);
        int qi = ((int)q) & 3;
        float v = (qi & 1) ? sinf(r) : cosf(r);
        float c = (qi == 1 || qi == 2) ? -v : v;
        float s = (k == 0) ? 0.03125f : 0.044194173824159216f;
        g_Mt[idx] = c * s;
    } else if (bx < 4104) {                        // pos-emb partial sums (32 tokens each)
        int p = bx - 4096;
#pragma unroll
        for (int qq = 0; qq < 4; qq++) {
            int d = tid + qq * 256;
            float s = 0.f;
#pragma unroll 4
            for (int t = 0; t < 32; t++) s += pos[(p * 32 + t) * 1024 + d];
            g_mpart[p * 1024 + d] = s;
        }
    } else {                                       // wofc = Wo @ Wfc (2 warps per row)
        int bl = bx - 4104;
        int row = bl * 4 + (tid >> 6);
        int l64 = tid & 63;
        const float* wr = Wo + (size_t)row * 1024;
        float s = 0.f;
#pragma unroll 16
        for (int it = 0; it < 16; it++) s += wr[it * 64 + l64] * Wfc[it * 64 + l64];
        for (int o = 16; o; o >>= 1) s += __shfl_xor_sync(0xffffffffu, s, o);
        __shared__ float ss[8];
        if (!(tid & 31)) ss[tid >> 5] = s;
        __syncthreads();
        if (tid < 4) g_wofc[bl * 4 + tid] = ss[2 * tid] + ss[2 * tid + 1];
    }
}
__global__ void __launch_bounds__(256) k_wvofc(const float* __restrict__ Wv) {
    int row = blockIdx.x * 4 + (threadIdx.x >> 6), l64 = threadIdx.x & 63;
    const float* wr = Wv + (size_t)row * 1024;
    float s = 0.f;
#pragma unroll 16
    for (int it = 0; it < 16; it++) s += wr[it * 64 + l64] * g_wofc[it * 64 + l64];
    for (int o = 16; o; o >>= 1) s += __shfl_xor_sync(0xffffffffu, s, o);
    __shared__ float ss[8];
    if (!(threadIdx.x & 31)) ss[threadIdx.x >> 5] = s;
    __syncthreads();
    if (threadIdx.x < 4) g_wvofc[blockIdx.x * 4 + threadIdx.x] = ss[2 * threadIdx.x] + ss[2 * threadIdx.x + 1];
}

// ---------- fused per-plane: load to smem, pools + orig bins + shuffled bins ----------
__global__ void __launch_bounds__(1024) k_planes(const float* __restrict__ x,
                                                 const int* __restrict__ sidx,
                                                 const int* __restrict__ rot,
                                                 const int* __restrict__ fh,
                                                 const int* __restrict__ fw) {
    extern __shared__ float sm[];
    float* pl = sm;                 // 224 rows x 225 stride
    float* p4 = sm + 225 * 224;     // 56x56
    int bc = blockIdx.x, b = bc / 3, c = bc % 3, tid = threadIdx.x;
    const float* plane = x + (size_t)bc * 50176;

    __shared__ int sm_m[49], sm_k[49], sm_h[49], sm_w[49];
    if (tid < 49) {
        sm_m[tid] = sidx[tid];
        sm_k[tid] = rot[b * 49 + tid];
        sm_h[tid] = fh[b * 49 + tid];
        sm_w[tid] = fw[b * 49 + tid];
    }
    for (int idx = tid; idx < 50176; idx += 1024) {
        int i = idx / 224, j = idx - i * 224;
        pl[i * 225 + j] = plane[idx];
    }
    __syncthreads();
    for (int cell = tid; cell < 3136; cell += 1024) {
        int i = cell / 56, j = cell - (cell / 56) * 56;
        const float* p = pl + (i * 4) * 225 + j * 4;
        float s = 0.f;
#pragma unroll
        for (int r = 0; r < 4; r++)
            s += p[r * 225] + p[r * 225 + 1] + p[r * 225 + 2] + p[r * 225 + 3];
        p4[cell] = s;
    }
    __syncthreads();
    for (int cell = tid; cell < 3136; cell += 1024) {
        int i = cell / 56, j = cell - (cell / 56) * 56;
        int i0 = i & ~1, j0 = j & ~1;
        float s8 = p4[i0 * 56 + j0] + p4[i0 * 56 + j0 + 1] +
                   p4[(i0 + 1) * 56 + j0] + p4[(i0 + 1) * 56 + j0 + 1];
        g_npool[(size_t)bc * 3136 + cell] = p4[cell] * 0.0625f - s8 * 0.015625f;
    }
    if (tid < 196) {                               // original-branch bins
        int dy = tid / 14, dx = tid - (tid / 14) * 14;
        float s = 0.f;
        for (int ii = 0; ii < 16; ii++) {
            const float* row = pl + (ii * 14 + dy) * 225;
#pragma unroll
            for (int jj = 0; jj < 16; jj++) s += row[jj * 14 + dx];
        }
        g_meanO[b * 588 + c * 196 + tid] = s * (1.0f / 256.0f);
    } else if (tid >= 256 && tid < 452) {          // shuffled-branch bins (inverse map)
        int bin = tid - 256, dy = bin / 14, dx = bin - (bin / 14) * 14;
        float s = 0.f;
        for (int ii = 0; ii < 16; ii++) {
            int y = ii * 14 + dy;
            int pr = y >> 5, r = y & 31;
#pragma unroll 4
            for (int jj = 0; jj < 16; jj++) {
                int xx = jj * 14 + dx;
                int pc = xx >> 5, cc = xx & 31;
                int n = pr * 7 + pc;
                int m = sm_m[n];
                int c1 = sm_w[n] ? 31 - cc : cc;
                int r1 = sm_h[n] ? 31 - r : r;
                int k = sm_k[n], sr, sc;
                if (k == 0)      { sr = r1;      sc = c1;      }
                else if (k == 1) { sr = c1;      sc = 31 - r1; }
                else if (k == 2) { sr = 31 - r1; sc = 31 - c1; }
                else             { sr = 31 - c1; sc = r1;      }
                s += pl[((m / 7) * 32 + sr) * 225 + (m % 7) * 32 + sc];
            }
        }
        g_meanS[b * 588 + c * 196 + bin] = s * (1.0f / 256.0f);
    }
}

// ---------- GEMM body: 64 rows x 128 cols per block, packed f32x2, no repacking ----------
__device__ __forceinline__ void gemm_body(const float* __restrict__ A, const float* __restrict__ W,
                                          float* __restrict__ po, int K, int kbeg, int kend,
                                          float* a_sm) {
    int tid = threadIdx.x;
    int c0 = blockIdx.x * 128 + (tid & 63);
    int row0 = (tid >> 6) * 16;
    unsigned long long acc[16];
#pragma unroll
    for (int i = 0; i < 16; i++) acc[i] = 0ULL;
    for (int k0 = kbeg; k0 < kend; k0 += 16) {
        int cb = min(16, kend - k0);
        __syncthreads();
        for (int idx = tid; idx < 1024; idx += 256) {
            int m = idx >> 4, kk = idx & 15;
            a_sm[kk * 68 + m] = (kk < cb) ? A[(size_t)m * K + k0 + kk] : 0.f;
        }
        __syncthreads();
        const float* wp = W + (size_t)k0 * 1024 + c0;
#pragma unroll 4
        for (int kk = 0; kk < cb; kk++) {
            float w0 = wp[0];
            float w1 = wp[64];
            wp += 1024;
            unsigned long long w0x = pk2(w0, w0), w1x = pk2(w1, w1);
            const ulonglong2* ap = reinterpret_cast<const ulonglong2*>(a_sm + kk * 68 + row0);
            ulonglong2 v0 = ap[0], v1 = ap[1], v2 = ap[2], v3 = ap[3];
            fma2(acc[0], v0.x, w0x); fma2(acc[1], v0.y, w0x);
            fma2(acc[2], v1.x, w0x); fma2(acc[3], v1.y, w0x);
            fma2(acc[4], v2.x, w0x); fma2(acc[5], v2.y, w0x);
            fma2(acc[6], v3.x, w0x); fma2(acc[7], v3.y, w0x);
            fma2(acc[8],  v0.x, w1x); fma2(acc[9],  v0.y, w1x);
            fma2(acc[10], v1.x, w1x); fma2(acc[11], v1.y, w1x);
            fma2(acc[12], v2.x, w1x); fma2(acc[13], v2.y, w1x);
            fma2(acc[14], v3.x, w1x); fma2(acc[15], v3.y, w1x);
        }
    }
#pragma unroll
    for (int j = 0; j < 8; j++) {
        unsigned lo, hi;
        asm("mov.b64 {%0,%1}, %2;" : "=r"(lo), "=r"(hi) : "l"(acc[j]));
        po[(size_t)(row0 + 2 * j) * 1024 + c0] = __uint_as_float(lo);
        po[(size_t)(row0 + 2 * j + 1) * 1024 + c0] = __uint_as_float(hi);
        asm("mov.b64 {%0,%1}, %2;" : "=r"(lo), "=r"(hi) : "l"(acc[8 + j]));
        po[(size_t)(row0 + 2 * j) * 1024 + c0 + 64] = __uint_as_float(lo);
        po[(size_t)(row0 + 2 * j + 1) * 1024 + c0 + 64] = __uint_as_float(hi);
    }
}

// merged branch(2 mats, K=588, S=12) + noise(K=9408, S=48)
__global__ void __launch_bounds__(256) k_gemm_bn(const float* __restrict__ W_pe,
                                                 const float* __restrict__ W_no) {
    __shared__ __align__(16) float a_sm[16 * 68];
    int z = blockIdx.z;
    if (z < 24) {
        int mat = z / 12, y = z - mat * 12;
        const float* A = mat ? g_meanO : g_meanS;
        gemm_body(A, W_pe, g_part + (size_t)z * 65536, 588, y * 49, y * 49 + 49, a_sm);
    } else {
        int y = z - 24;
        gemm_body(g_npool, W_no, g_part + 1572864 + (size_t)y * 65536, 9408, y * 196, y * 196 + 196, a_sm);
    }
}
// generic: asel 3=g_feats 4=g_t
__global__ void __launch_bounds__(256) k_gemm(int asel, const float* __restrict__ W0,
                                              const float* __restrict__ W1, int use_Mt,
                                              int K, int S, int nrt) {
    __shared__ __align__(16) float a_sm[16 * 68];
    int z = blockIdx.z;
    int mat = z / nrt, rt = z - mat * nrt;
    const float* A = ((asel == 3) ? g_feats : g_t) + (size_t)(rt * 64) * K;
    const float* W = use_Mt ? g_Mt : (mat ? W1 : W0);
    int kslice = K / S, kbeg = blockIdx.y * kslice;
    float* po = g_part + ((size_t)(mat * S + blockIdx.y) * nrt + rt) * 65536;
    gemm_body(A, W, po, K, kbeg, kbeg + kslice, a_sm);
}

// ---------- merged reduce: branch LN (+pos-emb) and noise ----------
__global__ void __launch_bounds__(256) k_reduce_bn(const float* __restrict__ gg,
                                                   const float* __restrict__ bb) {
    int bx = blockIdx.x;
    if (bx < 128) {
        int z = bx >> 6, b = bx & 63;
        const float* base = g_part + (size_t)z * 12 * 65536 + (size_t)b * 1024;
        float v[4], s = 0.f, q = 0.f;
#pragma unroll
        for (int i = 0; i < 4; i++) {
            int d = threadIdx.x + i * 256;
            float mp = 0.f;
#pragma unroll
            for (int p = 0; p < 8; p++) mp += g_mpart[p * 1024 + d];
            float xv = mp * (1.0f / 256.0f);
#pragma unroll
            for (int y = 0; y < 12; y++) xv += base[(size_t)y * 65536 + d];
            v[i] = xv; s += xv; q += xv * xv;
        }
        s = blk_sum256(s); q = blk_sum256(q);
        float mean = s * (1.0f / 1024.0f);
        float inv = rsqrtf(q * (1.0f / 1024.0f) - mean * mean + 1e-5f);
#pragma unroll
        for (int i = 0; i < 4; i++) {
            int d = threadIdx.x + i * 256;
            g_feats[((size_t)b * 3 + z) * 1024 + d] = (v[i] - mean) * inv * gg[d] + bb[d];
        }
    } else {
        int i = (bx - 128) * 256 + threadIdx.x;    // 65536 noise elements
        float s = 0.f;
#pragma unroll
        for (int y = 0; y < 48; y++) s += g_part[1572864 + (size_t)y * 65536 + i];
        int b = i >> 10, d = i & 1023;
        g_feats[((size_t)b * 3 + 2) * 1024 + d] = s;
    }
}

// ---------- token LN + inline 16-way DCT partial reduce + fc/vproj dots ----------
__global__ void __launch_bounds__(256) k_ln_tokens(const float* __restrict__ gg,
                                                   const float* __restrict__ bb,
                                                   const float* __restrict__ wfc) {
    int r = blockIdx.x;
    float x[4], s = 0.f, q = 0.f;
#pragma unroll
    for (int i = 0; i < 4; i++) {
        int d = threadIdx.x + i * 256;
        float xv = 0.f;
#pragma unroll
        for (int y = 0; y < 16; y++) xv += g_part[(size_t)y * 196608 + (size_t)r * 1024 + d];
        x[i] = xv; s += xv; q += xv * xv;
    }
    s = blk_sum256(s); q = blk_sum256(q);
    float mean = s * (1.0f / 1024.0f);
    float inv = rsqrtf(q * (1.0f / 1024.0f) - mean * mean + 1e-5f);
    float dt = 0.f, dv = 0.f;
#pragma unroll
    for (int i = 0; i < 4; i++) {
        int d = threadIdx.x + i * 256;
        float tv = (x[i] - mean) * inv * gg[d] + bb[d];
        g_t[(size_t)r * 1024 + d] = tv;
        dt += x[i] * wfc[d];
        dv += tv * g_wvofc[d];
    }
    dt = blk_sum256(dt); dv = blk_sum256(dv);
    if (threadIdx.x == 0) { g_tokfc[r] = dt; g_vproj[r] = dv; }
}

// ---------- final: inline 8-way q/k partial reduce + 3x3 attention ----------
__global__ void __launch_bounds__(256) k_final(const float* __restrict__ bfc,
                                               float* __restrict__ out) {
    int b = blockIdx.x, tid = threadIdx.x;
    float a9[9];
#pragma unroll
    for (int p = 0; p < 9; p++) a9[p] = 0.f;
#pragma unroll
    for (int i = 0; i < 4; i++) {
        int d = tid + i * 256;
        float qv[3], kv[3];
#pragma unroll
        for (int n = 0; n < 3; n++) {
            size_t base = (size_t)(b * 3 + n) * 1024 + d;
            float sq = 0.f, sk = 0.f;
#pragma unroll
            for (int y = 0; y < 8; y++) {
                sq += g_part[(size_t)y * 196608 + base];
                sk += g_part[1572864 + (size_t)y * 196608 + base];
            }
            qv[n] = sq; kv[n] = sk;
        }
#pragma unroll
        for (int n = 0; n < 3; n++)
#pragma unroll
            for (int m = 0; m < 3; m++) a9[n * 3 + m] += qv[n] * kv[m];
    }
    __shared__ float red[8 * 9];
    int lane = tid & 31, w = tid >> 5;
#pragma unroll
    for (int p = 0; p < 9; p++) {
        float v = a9[p];
        for (int o = 16; o; o >>= 1) v += __shfl_xor_sync(0xffffffffu, v, o);
        if (!lane) red[w * 9 + p] = v;
    }
    __syncthreads();
    if (tid == 0) {
        float s[9];
#pragma unroll
        for (int p = 0; p < 9; p++) {
            float v = 0.f;
#pragma unroll
            for (int ww = 0; ww < 8; ww++) v += red[ww * 9 + p];
            s[p] = v;
        }
        float w0 = 0.f, w1 = 0.f, w2 = 0.f;
#pragma unroll
        for (int n = 0; n < 3; n++) {
            float a = s[n * 3] * 0.03125f, c = s[n * 3 + 1] * 0.03125f, e = s[n * 3 + 2] * 0.03125f;
            float mx = fmaxf(a, fmaxf(c, e));
            float e0 = expf(a - mx), e1 = expf(c - mx), e2 = expf(e - mx);
            float is = 1.0f / (e0 + e1 + e2);
            w0 += e0 * is; w1 += e1 * is; w2 += e2 * is;
        }
        float r = (w0 * g_vproj[b * 3] + w1 * g_vproj[b * 3 + 1] + w2 * g_vproj[b * 3 + 2]) * (1.0f / 3.0f);
        r += (g_tokfc[b * 3] + g_tokfc[b * 3 + 1] + g_tokfc[b * 3 + 2]) * (1.0f / 3.0f);
        out[b] = r + bfc[0];
    }
}

// ---------- launch ----------
extern "C" void kernel_launch(void* const* d_in, const int* in_sizes, int n_in,
                              void* d_out, int out_size) {
    (void)in_sizes; (void)n_in; (void)out_size;
    const float* x    = (const float*)d_in[0];
    const int*   sidx = (const int*)d_in[1];
    const int*   rot  = (const int*)d_in[2];
    const int*   fh   = (const int*)d_in[3];
    const int*   fw   = (const int*)d_in[4];
    const float* W_pe = (const float*)d_in[5];
    const float* pos  = (const float*)d_in[6];
    const float* ln_g = (const float*)d_in[7];
    const float* ln_b = (const float*)d_in[8];
    const float* W_no = (const float*)d_in[9];
    const float* Wq   = (const float*)d_in[10];
    const float* Wk   = (const float*)d_in[11];
    const float* Wv   = (const float*)d_in[12];
    const float* Wo   = (const float*)d_in[13];
    const float* ah_g = (const float*)d_in[14];
    const float* ah_b = (const float*)d_in[15];
    const float* W_fc = (const float*)d_in[16];
    const float* b_fc = (const float*)d_in[17];
    float* out = (float*)d_out;

    cudaFuncSetAttribute(k_planes, cudaFuncAttributeMaxDynamicSharedMemorySize, 215040);

    k_setup<<<4360, 256>>>(pos, Wo, W_fc);
    k_wvofc<<<256, 256>>>(Wv);
    k_planes<<<192, 1024, 214144>>>(x, sidx, rot, fh, fw);
    k_gemm_bn<<<dim3(8, 1, 72), 256>>>(W_pe, W_no);
    k_reduce_bn<<<384, 256>>>(ln_g, ln_b);
    k_gemm<<<dim3(8, 16, 3), 256>>>(3, W_pe, W_pe, 1, 1024, 16, 3);  // DCT
    k_ln_tokens<<<192, 256>>>(ah_g, ah_b, W_fc);
    k_gemm<<<dim3(8, 8, 6), 256>>>(4, Wq, Wk, 0, 1024, 8, 3);        // q,k
    k_final<<<64, 256>>>(b_fc, out);
}

// round 9
// speedup vs baseline: 1.6837x; 1.2304x over previous
#include <cuda_runtime.h>
#include <cuda_bf16.h>

// ---------- static device scratch ----------
__device__ float g_Mt[1024 * 1024];
__device__ float g_mpart[8 * 1024];
__device__ float g_meanS[64 * 588];
__device__ float g_meanO[64 * 588];
__device__ float g_npool[64 * 9408];
__device__ float g_part[4718592];
__device__ float g_feats[64 * 3 * 1024];
__device__ float g_t[192 * 1024];
__device__ float g_wofc[1024];
__device__ float g_wvofc[1024];
__device__ float g_vproj[192];
__device__ float g_tokfc[192];

// ---------- helpers ----------
__device__ __forceinline__ unsigned long long pk2(float lo, float hi) {
    unsigned long long r;
    asm("mov.b64 %0,{%1,%2};" : "=l"(r) : "r"(__float_as_uint(lo)), "r"(__float_as_uint(hi)));
    return r;
}
__device__ __forceinline__ void fma2(unsigned long long& acc, unsigned long long a, unsigned long long b) {
    asm("fma.rn.f32x2 %0, %1, %2, %0;" : "+l"(acc) : "l"(a), "l"(b));
}
__device__ __forceinline__ float blk_sum256(float v) {
    __shared__ float sb[8];
    int lane = threadIdx.x & 31, w = threadIdx.x >> 5;
    for (int o = 16; o; o >>= 1) v += __shfl_xor_sync(0xffffffffu, v, o);
    if (!lane) sb[w] = v;
    __syncthreads();
    float t = 0.f;
#pragma unroll
    for (int i = 0; i < 8; i++) t += sb[i];
    __syncthreads();
    return t;
}

// ---------- fused setup: DCT matrix + pos-emb partials + Wo@Wfc ----------
__global__ void __launch_bounds__(256) k_setup(const float* __restrict__ pos,
                                               const float* __restrict__ Wo,
                                               const float* __restrict__ Wfc) {
    int bx = blockIdx.x, tid = threadIdx.x;
    if (bx < 4096) {                               // DCT matrix, JAX fp32 arg rounding
        int idx = bx * 256 + tid;
        int d = idx >> 10, k = idx & 1023;
        float t1 = __fmul_rn(3.14159265358979323846f, (float)d + 0.5f);
        float t2 = __fmul_rn(t1, (float)k);
        float t3 = __fmul_rn(t2, 0.0009765625f);
        float q = rintf(t3 * 0.6366197723675814f);
        float r = __fmaf_rn(q, -1.57079637050628662109375f, t3);
        r = __fmaf_rn(q, 4.37113900018624283e-8f, r);
        int qi = ((int)q) & 3;
        float v = (qi & 1) ? sinf(r) : cosf(r);
        float c = (qi == 1 || qi == 2) ? -v : v;
        float s = (k == 0) ? 0.03125f : 0.044194173824159216f;
        g_Mt[idx] = c * s;
    } else if (bx < 4104) {                        // pos-emb partial sums (32 tokens each)
        int p = bx - 4096;
#pragma unroll
        for (int qq = 0; qq < 4; qq++) {
            int d = tid + qq * 256;
            float s = 0.f;
#pragma unroll 4
            for (int t = 0; t < 32; t++) s += pos[(p * 32 + t) * 1024 + d];
            g_mpart[p * 1024 + d] = s;
        }
    } else {                                       // wofc = Wo @ Wfc (2 warps per row)
        int bl = bx - 4104;
        int row = bl * 4 + (tid >> 6);
        int l64 = tid & 63;
        const float* wr = Wo + (size_t)row * 1024;
        float s = 0.f;
#pragma unroll 16
        for (int it = 0; it < 16; it++) s += wr[it * 64 + l64] * Wfc[it * 64 + l64];
        for (int o = 16; o; o >>= 1) s += __shfl_xor_sync(0xffffffffu, s, o);
        __shared__ float ss[8];
        if (!(tid & 31)) ss[tid >> 5] = s;
        __syncthreads();
        if (tid < 4) g_wofc[bl * 4 + tid] = ss[2 * tid] + ss[2 * tid + 1];
    }
}
__global__ void __launch_bounds__(256) k_wvofc(const float* __restrict__ Wv) {
    int row = blockIdx.x * 4 + (threadIdx.x >> 6), l64 = threadIdx.x & 63;
    const float* wr = Wv + (size_t)row * 1024;
    float s = 0.f;
#pragma unroll 16
    for (int it = 0; it < 16; it++) s += wr[it * 64 + l64] * g_wofc[it * 64 + l64];
    for (int o = 16; o; o >>= 1) s += __shfl_xor_sync(0xffffffffu, s, o);
    __shared__ float ss[8];
    if (!(threadIdx.x & 31)) ss[threadIdx.x >> 5] = s;
    __syncthreads();
    if (threadIdx.x < 4) g_wvofc[blockIdx.x * 4 + threadIdx.x] = ss[2 * threadIdx.x] + ss[2 * threadIdx.x + 1];
}

// ---------- fused per-plane: load to smem, pools + orig bins + shuffled bins ----------
__global__ void __launch_bounds__(1024) k_planes(const float* __restrict__ x,
                                                 const int* __restrict__ sidx,
                                                 const int* __restrict__ rot,
                                                 const int* __restrict__ fh,
                                                 const int* __restrict__ fw) {
    extern __shared__ float sm[];
    float* pl = sm;                 // 224 rows x 225 stride
    float* p4 = sm + 225 * 224;     // 56x56
    int bc = blockIdx.x, b = bc / 3, c = bc % 3, tid = threadIdx.x;
    const float* plane = x + (size_t)bc * 50176;

    __shared__ int sm_m[49], sm_k[49], sm_h[49], sm_w[49];
    if (tid < 49) {
        sm_m[tid] = sidx[tid];
        sm_k[tid] = rot[b * 49 + tid];
        sm_h[tid] = fh[b * 49 + tid];
        sm_w[tid] = fw[b * 49 + tid];
    }
    for (int idx = tid; idx < 50176; idx += 1024) {
        int i = idx / 224, j = idx - i * 224;
        pl[i * 225 + j] = plane[idx];
    }
    __syncthreads();
    for (int cell = tid; cell < 3136; cell += 1024) {
        int i = cell / 56, j = cell - (cell / 56) * 56;
        const float* p = pl + (i * 4) * 225 + j * 4;
        float s = 0.f;
#pragma unroll
        for (int r = 0; r < 4; r++)
            s += p[r * 225] + p[r * 225 + 1] + p[r * 225 + 2] + p[r * 225 + 3];
        p4[cell] = s;
    }
    __syncthreads();
    for (int cell = tid; cell < 3136; cell += 1024) {
        int i = cell / 56, j = cell - (cell / 56) * 56;
        int i0 = i & ~1, j0 = j & ~1;
        float s8 = p4[i0 * 56 + j0] + p4[i0 * 56 + j0 + 1] +
                   p4[(i0 + 1) * 56 + j0] + p4[(i0 + 1) * 56 + j0 + 1];
        g_npool[(size_t)bc * 3136 + cell] = p4[cell] * 0.0625f - s8 * 0.015625f;
    }
    if (tid < 196) {                               // original-branch bins
        int dy = tid / 14, dx = tid - (tid / 14) * 14;
        float s = 0.f;
        for (int ii = 0; ii < 16; ii++) {
            const float* row = pl + (ii * 14 + dy) * 225;
#pragma unroll
            for (int jj = 0; jj < 16; jj++) s += row[jj * 14 + dx];
        }
        g_meanO[b * 588 + c * 196 + tid] = s * (1.0f / 256.0f);
    } else if (tid >= 256 && tid < 452) {          // shuffled-branch bins (inverse map)
        int bin = tid - 256, dy = bin / 14, dx = bin - (bin / 14) * 14;
        float s = 0.f;
        for (int ii = 0; ii < 16; ii++) {
            int y = ii * 14 + dy;
            int pr = y >> 5, r = y & 31;
#pragma unroll 4
            for (int jj = 0; jj < 16; jj++) {
                int xx = jj * 14 + dx;
                int pc = xx >> 5, cc = xx & 31;
                int n = pr * 7 + pc;
                int m = sm_m[n];
                int c1 = sm_w[n] ? 31 - cc : cc;
                int r1 = sm_h[n] ? 31 - r : r;
                int k = sm_k[n], sr, sc;
                if (k == 0)      { sr = r1;      sc = c1;      }
                else if (k == 1) { sr = c1;      sc = 31 - r1; }
                else if (k == 2) { sr = 31 - r1; sc = 31 - c1; }
                else             { sr = 31 - c1; sc = r1;      }
                s += pl[((m / 7) * 32 + sr) * 225 + (m % 7) * 32 + sc];
            }
        }
        g_meanS[b * 588 + c * 196 + bin] = s * (1.0f / 256.0f);
    }
}

// ---------- GEMM body: 64 rows x 128 cols per block; smem-staged A and W ----------
// REQUIREMENT: kbeg % 4 == 0 (float4 staging alignment); ragged tail handled by scalar path.
__device__ __forceinline__ void gemm_body(const float* __restrict__ A, const float* __restrict__ W,
                                          float* __restrict__ po, int K, int kbeg, int kend,
                                          float* a_sm, float* w_sm) {
    int tid = threadIdx.x;
    int cpair = tid & 63;
    int c0 = blockIdx.x * 128 + cpair * 2;
    int row0 = (tid >> 6) * 16;
    int am = tid >> 2, ak = (tid & 3) * 4;     // A staging: row am, 4 k's from ak
    int wr = tid >> 5, wc = (tid & 31) * 4;    // W staging: rows wr, wr+8; 4 cols from wc
    int cbase = blockIdx.x * 128;

    unsigned long long acc[16];
#pragma unroll
    for (int i = 0; i < 16; i++) acc[i] = 0ULL;

    int ntiles = (kend - kbeg + 15) >> 4;
    for (int t = 0; t < ntiles; t++) {
        int k0 = kbeg + t * 16;
        int cb = kend - k0; if (cb > 16) cb = 16;
        __syncthreads();
        if (cb == 16) {
            float4 a4 = *(const float4*)(A + (size_t)am * K + k0 + ak);
            float4 wA = *(const float4*)(W + (size_t)(k0 + wr) * 1024 + cbase + wc);
            float4 wB = *(const float4*)(W + (size_t)(k0 + wr + 8) * 1024 + cbase + wc);
            a_sm[(ak + 0) * 68 + am] = a4.x; a_sm[(ak + 1) * 68 + am] = a4.y;
            a_sm[(ak + 2) * 68 + am] = a4.z; a_sm[(ak + 3) * 68 + am] = a4.w;
            *(float4*)(w_sm + wr * 128 + wc) = wA;
            *(float4*)(w_sm + (wr + 8) * 128 + wc) = wB;
        } else {
#pragma unroll
            for (int i = 0; i < 4; i++)
                a_sm[(ak + i) * 68 + am] = (ak + i < cb) ? A[(size_t)am * K + k0 + ak + i] : 0.f;
#pragma unroll
            for (int i = 0; i < 4; i++) {
                w_sm[wr * 128 + wc + i] = (wr < cb) ? W[(size_t)(k0 + wr) * 1024 + cbase + wc + i] : 0.f;
                w_sm[(wr + 8) * 128 + wc + i] = (wr + 8 < cb) ? W[(size_t)(k0 + wr + 8) * 1024 + cbase + wc + i] : 0.f;
            }
        }
        __syncthreads();
#pragma unroll 4
        for (int kk = 0; kk < 16; kk++) {
            float2 w = ((const float2*)(w_sm + kk * 128))[cpair];
            unsigned long long w0x = pk2(w.x, w.x), w1x = pk2(w.y, w.y);
            const ulonglong2* ap = reinterpret_cast<const ulonglong2*>(a_sm + kk * 68 + row0);
            ulonglong2 v0 = ap[0], v1 = ap[1], v2 = ap[2], v3 = ap[3];
            fma2(acc[0], v0.x, w0x); fma2(acc[1], v0.y, w0x);
            fma2(acc[2], v1.x, w0x); fma2(acc[3], v1.y, w0x);
            fma2(acc[4], v2.x, w0x); fma2(acc[5], v2.y, w0x);
            fma2(acc[6], v3.x, w0x); fma2(acc[7], v3.y, w0x);
            fma2(acc[8],  v0.x, w1x); fma2(acc[9],  v0.y, w1x);
            fma2(acc[10], v1.x, w1x); fma2(acc[11], v1.y, w1x);
            fma2(acc[12], v2.x, w1x); fma2(acc[13], v2.y, w1x);
            fma2(acc[14], v3.x, w1x); fma2(acc[15], v3.y, w1x);
        }
    }
#pragma unroll
    for (int j = 0; j < 8; j++) {
        unsigned l0, h0, l1, h1;
        asm("mov.b64 {%0,%1}, %2;" : "=r"(l0), "=r"(h0) : "l"(acc[j]));
        asm("mov.b64 {%0,%1}, %2;" : "=r"(l1), "=r"(h1) : "l"(acc[8 + j]));
        float2 r0 = make_float2(__uint_as_float(l0), __uint_as_float(l1));
        float2 r1 = make_float2(__uint_as_float(h0), __uint_as_float(h1));
        *(float2*)(po + (size_t)(row0 + 2 * j) * 1024 + c0) = r0;
        *(float2*)(po + (size_t)(row0 + 2 * j + 1) * 1024 + c0) = r1;
    }
}

// merged branch(2 mats, K=588: 11 slices of 48 + 1 slice of 60, all 16-aligned starts)
// + noise(K=9408, S=42, slices of 224 = 14 exact tiles)
__global__ void __launch_bounds__(256) k_gemm_bn(const float* __restrict__ W_pe,
                                                 const float* __restrict__ W_no) {
    __shared__ __align__(16) float a_sm[16 * 68];
    __shared__ __align__(16) float w_sm[16 * 128];
    int z = blockIdx.z;
    if (z < 24) {
        int mat = z / 12, y = z - mat * 12;
        const float* A = mat ? g_meanO : g_meanS;
        int kbeg = y * 48;
        int kend = (y == 11) ? 588 : kbeg + 48;
        gemm_body(A, W_pe, g_part + (size_t)z * 65536, 588, kbeg, kend, a_sm, w_sm);
    } else {
        int y = z - 24;
        gemm_body(g_npool, W_no, g_part + 1572864 + (size_t)y * 65536, 9408, y * 224, y * 224 + 224, a_sm, w_sm);
    }
}
// generic: asel 3=g_feats 4=g_t
__global__ void __launch_bounds__(256) k_gemm(int asel, const float* __restrict__ W0,
                                              const float* __restrict__ W1, int use_Mt,
                                              int K, int S, int nrt) {
    __shared__ __align__(16) float a_sm[16 * 68];
    __shared__ __align__(16) float w_sm[16 * 128];
    int z = blockIdx.z;
    int mat = z / nrt, rt = z - mat * nrt;
    const float* A = ((asel == 3) ? g_feats : g_t) + (size_t)(rt * 64) * K;
    const float* W = use_Mt ? g_Mt : (mat ? W1 : W0);
    int kslice = K / S, kbeg = blockIdx.y * kslice;
    float* po = g_part + ((size_t)(mat * S + blockIdx.y) * nrt + rt) * 65536;
    gemm_body(A, W, po, K, kbeg, kbeg + kslice, a_sm, w_sm);
}

// ---------- merged reduce: branch LN (+pos-emb) and noise ----------
__global__ void __launch_bounds__(256) k_reduce_bn(const float* __restrict__ gg,
                                                   const float* __restrict__ bb) {
    int bx = blockIdx.x;
    if (bx < 128) {
        int z = bx >> 6, b = bx & 63;
        const float* base = g_part + (size_t)z * 12 * 65536 + (size_t)b * 1024;
        float v[4], s = 0.f, q = 0.f;
#pragma unroll
        for (int i = 0; i < 4; i++) {
            int d = threadIdx.x + i * 256;
            float mp = 0.f;
#pragma unroll
            for (int p = 0; p < 8; p++) mp += g_mpart[p * 1024 + d];
            float xv = mp * (1.0f / 256.0f);
#pragma unroll
            for (int y = 0; y < 12; y++) xv += base[(size_t)y * 65536 + d];
            v[i] = xv; s += xv; q += xv * xv;
        }
        s = blk_sum256(s); q = blk_sum256(q);
        float mean = s * (1.0f / 1024.0f);
        float inv = rsqrtf(q * (1.0f / 1024.0f) - mean * mean + 1e-5f);
#pragma unroll
        for (int i = 0; i < 4; i++) {
            int d = threadIdx.x + i * 256;
            g_feats[((size_t)b * 3 + z) * 1024 + d] = (v[i] - mean) * inv * gg[d] + bb[d];
        }
    } else {
        int i = (bx - 128) * 256 + threadIdx.x;    // 65536 noise elements
        float s = 0.f;
#pragma unroll
        for (int y = 0; y < 42; y++) s += g_part[1572864 + (size_t)y * 65536 + i];
        int b = i >> 10, d = i & 1023;
        g_feats[((size_t)b * 3 + 2) * 1024 + d] = s;
    }
}

// ---------- token LN + inline 16-way DCT partial reduce + fc/vproj dots ----------
__global__ void __launch_bounds__(256) k_ln_tokens(const float* __restrict__ gg,
                                                   const float* __restrict__ bb,
                                                   const float* __restrict__ wfc) {
    int r = blockIdx.x;
    float x[4], s = 0.f, q = 0.f;
#pragma unroll
    for (int i = 0; i < 4; i++) {
        int d = threadIdx.x + i * 256;
        float xv = 0.f;
#pragma unroll
        for (int y = 0; y < 16; y++) xv += g_part[(size_t)y * 196608 + (size_t)r * 1024 + d];
        x[i] = xv; s += xv; q += xv * xv;
    }
    s = blk_sum256(s); q = blk_sum256(q);
    float mean = s * (1.0f / 1024.0f);
    float inv = rsqrtf(q * (1.0f / 1024.0f) - mean * mean + 1e-5f);
    float dt = 0.f, dv = 0.f;
#pragma unroll
    for (int i = 0; i < 4; i++) {
        int d = threadIdx.x + i * 256;
        float tv = (x[i] - mean) * inv * gg[d] + bb[d];
        g_t[(size_t)r * 1024 + d] = tv;
        dt += x[i] * wfc[d];
        dv += tv * g_wvofc[d];
    }
    dt = blk_sum256(dt); dv = blk_sum256(dv);
    if (threadIdx.x == 0) { g_tokfc[r] = dt; g_vproj[r] = dv; }
}

// ---------- final: inline 8-way q/k partial reduce + 3x3 attention ----------
__global__ void __launch_bounds__(256) k_final(const float* __restrict__ bfc,
                                               float* __restrict__ out) {
    int b = blockIdx.x, tid = threadIdx.x;
    float a9[9];
#pragma unroll
    for (int p = 0; p < 9; p++) a9[p] = 0.f;
#pragma unroll
    for (int i = 0; i < 4; i++) {
        int d = tid + i * 256;
        float qv[3], kv[3];
#pragma unroll
        for (int n = 0; n < 3; n++) {
            size_t base = (size_t)(b * 3 + n) * 1024 + d;
            float sq = 0.f, sk = 0.f;
#pragma unroll
            for (int y = 0; y < 8; y++) {
                sq += g_part[(size_t)y * 196608 + base];
                sk += g_part[1572864 + (size_t)y * 196608 + base];
            }
            qv[n] = sq; kv[n] = sk;
        }
#pragma unroll
        for (int n = 0; n < 3; n++)
#pragma unroll
            for (int m = 0; m < 3; m++) a9[n * 3 + m] += qv[n] * kv[m];
    }
    __shared__ float red[8 * 9];
    int lane = tid & 31, w = tid >> 5;
#pragma unroll
    for (int p = 0; p < 9; p++) {
        float v = a9[p];
        for (int o = 16; o; o >>= 1) v += __shfl_xor_sync(0xffffffffu, v, o);
        if (!lane) red[w * 9 + p] = v;
    }
    __syncthreads();
    if (tid == 0) {
        float s[9];
#pragma unroll
        for (int p = 0; p < 9; p++) {
            float v = 0.f;
#pragma unroll
            for (int ww = 0; ww < 8; ww++) v += red[ww * 9 + p];
            s[p] = v;
        }
        float w0 = 0.f, w1 = 0.f, w2 = 0.f;
#pragma unroll
        for (int n = 0; n < 3; n++) {
            float a = s[n * 3] * 0.03125f, c = s[n * 3 + 1] * 0.03125f, e = s[n * 3 + 2] * 0.03125f;
            float mx = fmaxf(a, fmaxf(c, e));
            float e0 = expf(a - mx), e1 = expf(c - mx), e2 = expf(e - mx);
            float is = 1.0f / (e0 + e1 + e2);
            w0 += e0 * is; w1 += e1 * is; w2 += e2 * is;
        }
        float r = (w0 * g_vproj[b * 3] + w1 * g_vproj[b * 3 + 1] + w2 * g_vproj[b * 3 + 2]) * (1.0f / 3.0f);
        r += (g_tokfc[b * 3] + g_tokfc[b * 3 + 1] + g_tokfc[b * 3 + 2]) * (1.0f / 3.0f);
        out[b] = r + bfc[0];
    }
}

// ---------- launch ----------
extern "C" void kernel_launch(void* const* d_in, const int* in_sizes, int n_in,
                              void* d_out, int out_size) {
    (void)in_sizes; (void)n_in; (void)out_size;
    const float* x    = (const float*)d_in[0];
    const int*   sidx = (const int*)d_in[1];
    const int*   rot  = (const int*)d_in[2];
    const int*   fh   = (const int*)d_in[3];
    const int*   fw   = (const int*)d_in[4];
    const float* W_pe = (const float*)d_in[5];
    const float* pos  = (const float*)d_in[6];
    const float* ln_g = (const float*)d_in[7];
    const float* ln_b = (const float*)d_in[8];
    const float* W_no = (const float*)d_in[9];
    const float* Wq   = (const float*)d_in[10];
    const float* Wk   = (const float*)d_in[11];
    const float* Wv   = (const float*)d_in[12];
    const float* Wo   = (const float*)d_in[13];
    const float* ah_g = (const float*)d_in[14];
    const float* ah_b = (const float*)d_in[15];
    const float* W_fc = (const float*)d_in[16];
    const float* b_fc = (const float*)d_in[17];
    float* out = (float*)d_out;

    cudaFuncSetAttribute(k_planes, cudaFuncAttributeMaxDynamicSharedMemorySize, 215040);

    k_setup<<<4360, 256>>>(pos, Wo, W_fc);
    k_wvofc<<<256, 256>>>(Wv);
    k_planes<<<192, 1024, 214144>>>(x, sidx, rot, fh, fw);
    k_gemm_bn<<<dim3(8, 1, 66), 256>>>(W_pe, W_no);
    k_reduce_bn<<<384, 256>>>(ln_g, ln_b);
    k_gemm<<<dim3(8, 16, 3), 256>>>(3, W_pe, W_pe, 1, 1024, 16, 3);  // DCT
    k_ln_tokens<<<192, 256>>>(ah_g, ah_b, W_fc);
    k_gemm<<<dim3(8, 8, 6), 256>>>(4, Wq, Wk, 0, 1024, 8, 3);        // q,k
    k_final<<<64, 256>>>(b_fc, out);
}

// round 10
// speedup vs baseline: 1.8031x; 1.0709x over previous
#include <cuda_runtime.h>
#include <cuda_bf16.h>

// ---------- static device scratch ----------
__device__ float g_Mt[1024 * 1024];
__device__ float g_mpart[8 * 1024];
__device__ float g_meanS[64 * 588];
__device__ float g_meanO[64 * 588];
__device__ float g_npool[64 * 9408];
__device__ float g_part[4718592];
__device__ float g_feats[64 * 3 * 1024];
__device__ float g_t[192 * 1024];
__device__ float g_wofc[1024];
__device__ float g_wvofc[1024];
__device__ float g_vproj[192];
__device__ float g_tokfc[192];

// ---------- helpers ----------
__device__ __forceinline__ unsigned long long pk2(float lo, float hi) {
    unsigned long long r;
    asm("mov.b64 %0,{%1,%2};" : "=l"(r) : "r"(__float_as_uint(lo)), "r"(__float_as_uint(hi)));
    return r;
}
__device__ __forceinline__ void fma2(unsigned long long& acc, unsigned long long a, unsigned long long b) {
    asm("fma.rn.f32x2 %0, %1, %2, %0;" : "+l"(acc) : "l"(a), "l"(b));
}
__device__ __forceinline__ float blk_sum256(float v) {
    __shared__ float sb[8];
    int lane = threadIdx.x & 31, w = threadIdx.x >> 5;
    for (int o = 16; o; o >>= 1) v += __shfl_xor_sync(0xffffffffu, v, o);
    if (!lane) sb[w] = v;
    __syncthreads();
    float t = 0.f;
#pragma unroll
    for (int i = 0; i < 8; i++) t += sb[i];
    __syncthreads();
    return t;
}

// ---------- fused setup: DCT matrix + pos-emb partials + Wo@Wfc ----------
__global__ void __launch_bounds__(256) k_setup(const float* __restrict__ pos,
                                               const float* __restrict__ Wo,
                                               const float* __restrict__ Wfc) {
    int bx = blockIdx.x, tid = threadIdx.x;
    if (bx < 4096) {                               // DCT matrix, JAX fp32 arg rounding
        int idx = bx * 256 + tid;
        int d = idx >> 10, k = idx & 1023;
        float t1 = __fmul_rn(3.14159265358979323846f, (float)d + 0.5f);
        float t2 = __fmul_rn(t1, (float)k);
        float t3 = __fmul_rn(t2, 0.0009765625f);
        float q = rintf(t3 * 0.6366197723675814f);
        float r = __fmaf_rn(q, -1.57079637050628662109375f, t3);
        r = __fmaf_rn(q, 4.37113900018624283e-8f, r);
        int qi = ((int)q) & 3;
        float v = (qi & 1) ? sinf(r) : cosf(r);
        float c = (qi == 1 || qi == 2) ? -v : v;
        float s = (k == 0) ? 0.03125f : 0.044194173824159216f;
        g_Mt[idx] = c * s;
    } else if (bx < 4104) {                        // pos-emb partial sums (32 tokens each)
        int p = bx - 4096;
#pragma unroll
        for (int qq = 0; qq < 4; qq++) {
            int d = tid + qq * 256;
            float s = 0.f;
#pragma unroll 4
            for (int t = 0; t < 32; t++) s += pos[(p * 32 + t) * 1024 + d];
            g_mpart[p * 1024 + d] = s;
        }
    } else {                                       // wofc = Wo @ Wfc (2 warps per row)
        int bl = bx - 4104;
        int row = bl * 4 + (tid >> 6);
        int l64 = tid & 63;
        const float* wr = Wo + (size_t)row * 1024;
        float s = 0.f;
#pragma unroll 16
        for (int it = 0; it < 16; it++) s += wr[it * 64 + l64] * Wfc[it * 64 + l64];
        for (int o = 16; o; o >>= 1) s += __shfl_xor_sync(0xffffffffu, s, o);
        __shared__ float ss[8];
        if (!(tid & 31)) ss[tid >> 5] = s;
        __syncthreads();
        if (tid < 4) g_wofc[bl * 4 + tid] = ss[2 * tid] + ss[2 * tid + 1];
    }
}
__global__ void __launch_bounds__(256) k_wvofc(const float* __restrict__ Wv) {
    int row = blockIdx.x * 4 + (threadIdx.x >> 6), l64 = threadIdx.x & 63;
    const float* wr = Wv + (size_t)row * 1024;
    float s = 0.f;
#pragma unroll 16
    for (int it = 0; it < 16; it++) s += wr[it * 64 + l64] * g_wofc[it * 64 + l64];
    for (int o = 16; o; o >>= 1) s += __shfl_xor_sync(0xffffffffu, s, o);
    __shared__ float ss[8];
    if (!(threadIdx.x & 31)) ss[threadIdx.x >> 5] = s;
    __syncthreads();
    if (threadIdx.x < 4) g_wvofc[blockIdx.x * 4 + threadIdx.x] = ss[2 * threadIdx.x] + ss[2 * threadIdx.x + 1];
}

// ---------- fused per-plane: float4 load to smem, pools + orig bins + shuffled bins ----------
__global__ void __launch_bounds__(1024) k_planes(const float* __restrict__ x,
                                                 const int* __restrict__ sidx,
                                                 const int* __restrict__ rot,
                                                 const int* __restrict__ fh,
                                                 const int* __restrict__ fw) {
    extern __shared__ float sm[];
    float* pl = sm;                 // 224 rows x 228 stride (16B-aligned rows)
    float* p4 = sm + 228 * 224;     // 56x56
    int bc = blockIdx.x, b = bc / 3, c = bc % 3, tid = threadIdx.x;
    const float* plane = x + (size_t)bc * 50176;

    __shared__ int sm_m[49], sm_k[49], sm_h[49], sm_w[49];
    if (tid < 49) {
        sm_m[tid] = sidx[tid];
        sm_k[tid] = rot[b * 49 + tid];
        sm_h[tid] = fh[b * 49 + tid];
        sm_w[tid] = fw[b * 49 + tid];
    }
    for (int idx4 = tid; idx4 < 12544; idx4 += 1024) {      // 224*56 float4
        int i = idx4 / 56, j4 = idx4 - i * 56;
        *(float4*)(pl + i * 228 + j4 * 4) = *(const float4*)(plane + i * 224 + j4 * 4);
    }
    __syncthreads();
    for (int cell = tid; cell < 3136; cell += 1024) {
        int i = cell / 56, j = cell - (cell / 56) * 56;
        const float* p = pl + (i * 4) * 228 + j * 4;
        float s = 0.f;
#pragma unroll
        for (int r = 0; r < 4; r++)
            s += p[r * 228] + p[r * 228 + 1] + p[r * 228 + 2] + p[r * 228 + 3];
        p4[cell] = s;
    }
    __syncthreads();
    for (int cell = tid; cell < 3136; cell += 1024) {
        int i = cell / 56, j = cell - (cell / 56) * 56;
        int i0 = i & ~1, j0 = j & ~1;
        float s8 = p4[i0 * 56 + j0] + p4[i0 * 56 + j0 + 1] +
                   p4[(i0 + 1) * 56 + j0] + p4[(i0 + 1) * 56 + j0 + 1];
        g_npool[(size_t)bc * 3136 + cell] = p4[cell] * 0.0625f - s8 * 0.015625f;
    }
    if (tid < 196) {                               // original-branch bins
        int dy = tid / 14, dx = tid - (tid / 14) * 14;
        float s = 0.f;
        for (int ii = 0; ii < 16; ii++) {
            const float* row = pl + (ii * 14 + dy) * 228;
#pragma unroll
            for (int jj = 0; jj < 16; jj++) s += row[jj * 14 + dx];
        }
        g_meanO[b * 588 + c * 196 + tid] = s * (1.0f / 256.0f);
    } else if (tid >= 256 && tid < 452) {          // shuffled-branch bins (inverse map)
        int bin = tid - 256, dy = bin / 14, dx = bin - (bin / 14) * 14;
        float s = 0.f;
        for (int ii = 0; ii < 16; ii++) {
            int y = ii * 14 + dy;
            int pr = y >> 5, r = y & 31;
#pragma unroll 4
            for (int jj = 0; jj < 16; jj++) {
                int xx = jj * 14 + dx;
                int pc = xx >> 5, cc = xx & 31;
                int n = pr * 7 + pc;
                int m = sm_m[n];
                int c1 = sm_w[n] ? 31 - cc : cc;
                int r1 = sm_h[n] ? 31 - r : r;
                int k = sm_k[n], sr, sc;
                if (k == 0)      { sr = r1;      sc = c1;      }
                else if (k == 1) { sr = c1;      sc = 31 - r1; }
                else if (k == 2) { sr = 31 - r1; sc = 31 - c1; }
                else             { sr = 31 - c1; sc = r1;      }
                s += pl[((m / 7) * 32 + sr) * 228 + (m % 7) * 32 + sc];
            }
        }
        g_meanS[b * 588 + c * 196 + bin] = s * (1.0f / 256.0f);
    }
}

// ---------- GEMM body: 64 rows x 128 cols; double-buffered smem pipeline ----------
// REQUIREMENT: kbeg % 4 == 0. a_sm: 2*1088 floats, w_sm: 2*2048 floats.
__device__ __forceinline__ void gemm_body(const float* __restrict__ A, const float* __restrict__ W,
                                          float* __restrict__ po, int K, int kbeg, int kend,
                                          float* a_sm, float* w_sm) {
    int tid = threadIdx.x;
    int cpair = tid & 63;
    int c0 = blockIdx.x * 128 + cpair * 2;
    int row0 = (tid >> 6) * 16;
    int am = tid >> 2, ak = (tid & 3) * 4;
    int wr = tid >> 5, wc = (tid & 31) * 4;
    int cbase = blockIdx.x * 128;

    unsigned long long acc[16];
#pragma unroll
    for (int i = 0; i < 16; i++) acc[i] = 0ULL;

    int ntiles = (kend - kbeg + 15) >> 4;
    float4 a4, w4A, w4B;

    // ---- load tile t into registers ----
#define LOADT(t) do {                                                                  \
        int k0 = kbeg + (t) * 16;                                                      \
        int cb = kend - k0;                                                            \
        if (cb >= 16) {                                                                \
            a4  = *(const float4*)(A + (size_t)am * K + k0 + ak);                      \
            w4A = *(const float4*)(W + (size_t)(k0 + wr) * 1024 + cbase + wc);         \
            w4B = *(const float4*)(W + (size_t)(k0 + wr + 8) * 1024 + cbase + wc);     \
        } else {                                                                       \
            float av[4], wa[4], wb[4];                                                 \
            for (int i = 0; i < 4; i++) {                                              \
                av[i] = (ak + i < cb) ? A[(size_t)am * K + k0 + ak + i] : 0.f;         \
                wa[i] = (wr < cb) ? W[(size_t)(k0 + wr) * 1024 + cbase + wc + i] : 0.f;\
                wb[i] = (wr + 8 < cb) ? W[(size_t)(k0 + wr + 8) * 1024 + cbase + wc + i] : 0.f; \
            }                                                                          \
            a4 = make_float4(av[0], av[1], av[2], av[3]);                              \
            w4A = make_float4(wa[0], wa[1], wa[2], wa[3]);                             \
            w4B = make_float4(wb[0], wb[1], wb[2], wb[3]);                             \
        }                                                                              \
    } while (0)

    // ---- store registers into buffer ----
#define STORET(bsel) do {                                                              \
        float* as = a_sm + (bsel) * 1088;                                              \
        float* ws = w_sm + (bsel) * 2048;                                              \
        as[(ak + 0) * 68 + am] = a4.x; as[(ak + 1) * 68 + am] = a4.y;                  \
        as[(ak + 2) * 68 + am] = a4.z; as[(ak + 3) * 68 + am] = a4.w;                  \
        *(float4*)(ws + wr * 128 + wc) = w4A;                                          \
        *(float4*)(ws + (wr + 8) * 128 + wc) = w4B;                                    \
    } while (0)

    LOADT(0);
    STORET(0);
    __syncthreads();
    for (int t = 0; t < ntiles; t++) {
        if (t + 1 < ntiles) LOADT(t + 1);
        const float* as = a_sm + (t & 1) * 1088;
        const float* ws = w_sm + (t & 1) * 2048;
#pragma unroll 4
        for (int kk = 0; kk < 16; kk++) {
            float2 w = ((const float2*)(ws + kk * 128))[cpair];
            unsigned long long w0x = pk2(w.x, w.x), w1x = pk2(w.y, w.y);
            const ulonglong2* ap = reinterpret_cast<const ulonglong2*>(as + kk * 68 + row0);
            ulonglong2 v0 = ap[0], v1 = ap[1], v2 = ap[2], v3 = ap[3];
            fma2(acc[0], v0.x, w0x); fma2(acc[1], v0.y, w0x);
            fma2(acc[2], v1.x, w0x); fma2(acc[3], v1.y, w0x);
            fma2(acc[4], v2.x, w0x); fma2(acc[5], v2.y, w0x);
            fma2(acc[6], v3.x, w0x); fma2(acc[7], v3.y, w0x);
            fma2(acc[8],  v0.x, w1x); fma2(acc[9],  v0.y, w1x);
            fma2(acc[10], v1.x, w1x); fma2(acc[11], v1.y, w1x);
            fma2(acc[12], v2.x, w1x); fma2(acc[13], v2.y, w1x);
            fma2(acc[14], v3.x, w1x); fma2(acc[15], v3.y, w1x);
        }
        if (t + 1 < ntiles) STORET((t + 1) & 1);
        __syncthreads();
    }
#undef LOADT
#undef STORET
#pragma unroll
    for (int j = 0; j < 8; j++) {
        unsigned l0, h0, l1, h1;
        asm("mov.b64 {%0,%1}, %2;" : "=r"(l0), "=r"(h0) : "l"(acc[j]));
        asm("mov.b64 {%0,%1}, %2;" : "=r"(l1), "=r"(h1) : "l"(acc[8 + j]));
        float2 r0 = make_float2(__uint_as_float(l0), __uint_as_float(l1));
        float2 r1 = make_float2(__uint_as_float(h0), __uint_as_float(h1));
        *(float2*)(po + (size_t)(row0 + 2 * j) * 1024 + c0) = r0;
        *(float2*)(po + (size_t)(row0 + 2 * j + 1) * 1024 + c0) = r1;
    }
}

// merged noise-first(K=9408, S=42 x 224) + branch(2 mats, K=588: 11x48 + 60, 16-aligned)
__global__ void __launch_bounds__(256) k_gemm_bn(const float* __restrict__ W_pe,
                                                 const float* __restrict__ W_no) {
    __shared__ __align__(16) float a_sm[2 * 1088];
    __shared__ __align__(16) float w_sm[2 * 2048];
    int z = blockIdx.z;
    if (z < 42) {
        gemm_body(g_npool, W_no, g_part + 1572864 + (size_t)z * 65536, 9408, z * 224, z * 224 + 224, a_sm, w_sm);
    } else {
        int zz = z - 42;
        int mat = zz / 12, y = zz - mat * 12;
        const float* A = mat ? g_meanO : g_meanS;
        int kbeg = y * 48;
        int kend = (y == 11) ? 588 : kbeg + 48;
        gemm_body(A, W_pe, g_part + (size_t)zz * 65536, 588, kbeg, kend, a_sm, w_sm);
    }
}
// generic: asel 3=g_feats 4=g_t
__global__ void __launch_bounds__(256) k_gemm(int asel, const float* __restrict__ W0,
                                              const float* __restrict__ W1, int use_Mt,
                                              int K, int S, int nrt) {
    __shared__ __align__(16) float a_sm[2 * 1088];
    __shared__ __align__(16) float w_sm[2 * 2048];
    int z = blockIdx.z;
    int mat = z / nrt, rt = z - mat * nrt;
    const float* A = ((asel == 3) ? g_feats : g_t) + (size_t)(rt * 64) * K;
    const float* W = use_Mt ? g_Mt : (mat ? W1 : W0);
    int kslice = K / S, kbeg = blockIdx.y * kslice;
    float* po = g_part + ((size_t)(mat * S + blockIdx.y) * nrt + rt) * 65536;
    gemm_body(A, W, po, K, kbeg, kbeg + kslice, a_sm, w_sm);
}

// ---------- merged reduce: branch LN (+pos-emb) and noise ----------
__global__ void __launch_bounds__(256) k_reduce_bn(const float* __restrict__ gg,
                                                   const float* __restrict__ bb) {
    int bx = blockIdx.x;
    if (bx < 128) {
        int z = bx >> 6, b = bx & 63;
        const float* base = g_part + (size_t)z * 12 * 65536 + (size_t)b * 1024;
        float v[4], s = 0.f, q = 0.f;
#pragma unroll
        for (int i = 0; i < 4; i++) {
            int d = threadIdx.x + i * 256;
            float mp = 0.f;
#pragma unroll
            for (int p = 0; p < 8; p++) mp += g_mpart[p * 1024 + d];
            float xv = mp * (1.0f / 256.0f);
#pragma unroll
            for (int y = 0; y < 12; y++) xv += base[(size_t)y * 65536 + d];
            v[i] = xv; s += xv; q += xv * xv;
        }
        s = blk_sum256(s); q = blk_sum256(q);
        float mean = s * (1.0f / 1024.0f);
        float inv = rsqrtf(q * (1.0f / 1024.0f) - mean * mean + 1e-5f);
#pragma unroll
        for (int i = 0; i < 4; i++) {
            int d = threadIdx.x + i * 256;
            g_feats[((size_t)b * 3 + z) * 1024 + d] = (v[i] - mean) * inv * gg[d] + bb[d];
        }
    } else {
        int i = (bx - 128) * 256 + threadIdx.x;    // 65536 noise elements
        float s = 0.f;
#pragma unroll
        for (int y = 0; y < 42; y++) s += g_part[1572864 + (size_t)y * 65536 + i];
        int b = i >> 10, d = i & 1023;
        g_feats[((size_t)b * 3 + 2) * 1024 + d] = s;
    }
}

// ---------- token LN + inline 16-way DCT partial reduce + fc/vproj dots ----------
__global__ void __launch_bounds__(256) k_ln_tokens(const float* __restrict__ gg,
                                                   const float* __restrict__ bb,
                                                   const float* __restrict__ wfc) {
    int r = blockIdx.x;
    float x[4], s = 0.f, q = 0.f;
#pragma unroll
    for (int i = 0; i < 4; i++) {
        int d = threadIdx.x + i * 256;
        float xv = 0.f;
#pragma unroll
        for (int y = 0; y < 16; y++) xv += g_part[(size_t)y * 196608 + (size_t)r * 1024 + d];
        x[i] = xv; s += xv; q += xv * xv;
    }
    s = blk_sum256(s); q = blk_sum256(q);
    float mean = s * (1.0f / 1024.0f);
    float inv = rsqrtf(q * (1.0f / 1024.0f) - mean * mean + 1e-5f);
    float dt = 0.f, dv = 0.f;
#pragma unroll
    for (int i = 0; i < 4; i++) {
        int d = threadIdx.x + i * 256;
        float tv = (x[i] - mean) * inv * gg[d] + bb[d];
        g_t[(size_t)r * 1024 + d] = tv;
        dt += x[i] * wfc[d];
        dv += tv * g_wvofc[d];
    }
    dt = blk_sum256(dt); dv = blk_sum256(dv);
    if (threadIdx.x == 0) { g_tokfc[r] = dt; g_vproj[r] = dv; }
}

// ---------- final: inline 8-way q/k partial reduce + 3x3 attention ----------
__global__ void __launch_bounds__(256) k_final(const float* __restrict__ bfc,
                                               float* __restrict__ out) {
    int b = blockIdx.x, tid = threadIdx.x;
    float a9[9];
#pragma unroll
    for (int p = 0; p < 9; p++) a9[p] = 0.f;
#pragma unroll
    for (int i = 0; i < 4; i++) {
        int d = tid + i * 256;
        float qv[3], kv[3];
#pragma unroll
        for (int n = 0; n < 3; n++) {
            size_t base = (size_t)(b * 3 + n) * 1024 + d;
            float sq = 0.f, sk = 0.f;
#pragma unroll
            for (int y = 0; y < 8; y++) {
                sq += g_part[(size_t)y * 196608 + base];
                sk += g_part[1572864 + (size_t)y * 196608 + base];
            }
            qv[n] = sq; kv[n] = sk;
        }
#pragma unroll
        for (int n = 0; n < 3; n++)
#pragma unroll
            for (int m = 0; m < 3; m++) a9[n * 3 + m] += qv[n] * kv[m];
    }
    __shared__ float red[8 * 9];
    int lane = tid & 31, w = tid >> 5;
#pragma unroll
    for (int p = 0; p < 9; p++) {
        float v = a9[p];
        for (int o = 16; o; o >>= 1) v += __shfl_xor_sync(0xffffffffu, v, o);
        if (!lane) red[w * 9 + p] = v;
    }
    __syncthreads();
    if (tid == 0) {
        float s[9];
#pragma unroll
        for (int p = 0; p < 9; p++) {
            float v = 0.f;
#pragma unroll
            for (int ww = 0; ww < 8; ww++) v += red[ww * 9 + p];
            s[p] = v;
        }
        float w0 = 0.f, w1 = 0.f, w2 = 0.f;
#pragma unroll
        for (int n = 0; n < 3; n++) {
            float a = s[n * 3] * 0.03125f, c = s[n * 3 + 1] * 0.03125f, e = s[n * 3 + 2] * 0.03125f;
            float mx = fmaxf(a, fmaxf(c, e));
            float e0 = expf(a - mx), e1 = expf(c - mx), e2 = expf(e - mx);
            float is = 1.0f / (e0 + e1 + e2);
            w0 += e0 * is; w1 += e1 * is; w2 += e2 * is;
        }
        float r = (w0 * g_vproj[b * 3] + w1 * g_vproj[b * 3 + 1] + w2 * g_vproj[b * 3 + 2]) * (1.0f / 3.0f);
        r += (g_tokfc[b * 3] + g_tokfc[b * 3 + 1] + g_tokfc[b * 3 + 2]) * (1.0f / 3.0f);
        out[b] = r + bfc[0];
    }
}

// ---------- launch ----------
extern "C" void kernel_launch(void* const* d_in, const int* in_sizes, int n_in,
                              void* d_out, int out_size) {
    (void)in_sizes; (void)n_in; (void)out_size;
    const float* x    = (const float*)d_in[0];
    const int*   sidx = (const int*)d_in[1];
    const int*   rot  = (const int*)d_in[2];
    const int*   fh   = (const int*)d_in[3];
    const int*   fw   = (const int*)d_in[4];
    const float* W_pe = (const float*)d_in[5];
    const float* pos  = (const float*)d_in[6];
    const float* ln_g = (const float*)d_in[7];
    const float* ln_b = (const float*)d_in[8];
    const float* W_no = (const float*)d_in[9];
    const float* Wq   = (const float*)d_in[10];
    const float* Wk   = (const float*)d_in[11];
    const float* Wv   = (const float*)d_in[12];
    const float* Wo   = (const float*)d_in[13];
    const float* ah_g = (const float*)d_in[14];
    const float* ah_b = (const float*)d_in[15];
    const float* W_fc = (const float*)d_in[16];
    const float* b_fc = (const float*)d_in[17];
    float* out = (float*)d_out;

    cudaFuncSetAttribute(k_planes, cudaFuncAttributeMaxDynamicSharedMemorySize, 217088);

    k_setup<<<4360, 256>>>(pos, Wo, W_fc);
    k_wvofc<<<256, 256>>>(Wv);
    k_planes<<<192, 1024, 216832>>>(x, sidx, rot, fh, fw);
    k_gemm_bn<<<dim3(8, 1, 66), 256>>>(W_pe, W_no);
    k_reduce_bn<<<384, 256>>>(ln_g, ln_b);
    k_gemm<<<dim3(8, 16, 3), 256>>>(3, W_pe, W_pe, 1, 1024, 16, 3);  // DCT
    k_ln_tokens<<<192, 256>>>(ah_g, ah_b, W_fc);
    k_gemm<<<dim3(8, 8, 6), 256>>>(4, Wq, Wk, 0, 1024, 8, 3);        // q,k
    k_final<<<64, 256>>>(b_fc, out);
}